// round 1
// baseline (speedup 1.0000x reference)
#include <cuda_runtime.h>
#include <math.h>

#define NN 50000
#define NE 800000
#define DD 64
#define HH 128
#define GG 128
#define NL 3

// ---------------- device scratch (no allocations allowed) ----------------
__device__ float g_x[NN * DD];        // node features (updated in place)
__device__ float g_AB[(size_t)NN * 256];  // [A(=x@W1a + b1) | B(=x@W1b)] per node
__device__ float g_aggr[(size_t)NN * HH]; // per-node message sum
__device__ float g_stats[2 * DD];     // BN col sums / sumsq
__device__ float g_pool[GG * DD];
__device__ float g_cnt[GG];

__device__ __forceinline__ float softplusf(float x) {
    return fmaxf(x, 0.0f) + log1pf(__expf(-fabsf(x)));
}

// ---------------- k0: embedding gather ----------------
__global__ void k0_embed(const int* __restrict__ az, const float* __restrict__ emb) {
    int idx = blockIdx.x * blockDim.x + threadIdx.x;
    if (idx >= NN * DD) return;
    int i = idx >> 6, c = idx & 63;
    g_x[idx] = emb[az[i] * DD + c];
}

// ---------------- zero kernels ----------------
__global__ void kzero_layer() {
    int i = blockIdx.x * blockDim.x + threadIdx.x;
    if (i < NN * HH) g_aggr[i] = 0.0f;
    if (i < 2 * DD) g_stats[i] = 0.0f;
}
__global__ void kzero_pool() {
    int i = blockIdx.x * blockDim.x + threadIdx.x;
    if (i < GG * DD) g_pool[i] = 0.0f;
    if (i < GG) g_cnt[i] = 0.0f;
}

// ---------------- k1: AB = x @ [W1a | W1b]  (A gets +b1) ----------------
// grid (ceil(N/64), 2), block 256. half=0 -> rows 0..63 of W1 (dst part, +b1)
//                                  half=1 -> rows 64..127 (src part)
__global__ void __launch_bounds__(256) k1_AB(int l, const float* __restrict__ W1,
                                             const float* __restrict__ b1) {
    __shared__ float xs[64 * 64];
    __shared__ float ws[32 * 128];
    int tid = threadIdx.x, tx = tid & 31, ty = tid >> 5;
    int n0 = blockIdx.x * 64;
    int half = blockIdx.y;

    for (int it = 0; it < 16; ++it) {
        int idx = tid + it * 256;           // 4096
        int i = idx >> 6, c = idx & 63;
        int node = n0 + i;
        xs[idx] = (node < NN) ? g_x[(size_t)node * DD + c] : 0.0f;
    }
    const float* Wp = W1 + ((size_t)l * 129 + half * 64) * 128;

    float acc[8][4] = {};
    for (int kc = 0; kc < 64; kc += 32) {
        __syncthreads();
        for (int it = 0; it < 16; ++it) {
            int idx = tid + it * 256;       // 4096
            ws[idx] = Wp[(size_t)kc * 128 + idx];
        }
        __syncthreads();
        #pragma unroll 8
        for (int k = 0; k < 32; ++k) {
            float bv[4];
            #pragma unroll
            for (int j = 0; j < 4; ++j) bv[j] = ws[k * 128 + tx + 32 * j];
            #pragma unroll
            for (int i = 0; i < 8; ++i) {
                float a = xs[(ty * 8 + i) * 64 + kc + k];
                #pragma unroll
                for (int j = 0; j < 4; ++j) acc[i][j] = fmaf(a, bv[j], acc[i][j]);
            }
        }
    }
    #pragma unroll
    for (int i = 0; i < 8; ++i) {
        int node = n0 + ty * 8 + i;
        if (node < NN) {
            #pragma unroll
            for (int j = 0; j < 4; ++j) {
                int c = tx + 32 * j;
                float v = acc[i][j];
                if (half == 0) v += b1[l * 128 + c];
                g_AB[(size_t)node * 256 + half * 128 + c] = v;
            }
        }
    }
}

// ---------------- k2: edge MLP (fused gather + GEMM2 + scatter) ----------------
// block = 256 threads, 64 edges per block. E % 64 == 0.
__global__ void __launch_bounds__(256) k2_edge(int l, const int* __restrict__ ei,
                                               const float* __restrict__ eattr,
                                               const float* __restrict__ W1,
                                               const float* __restrict__ W2,
                                               const float* __restrict__ b2) {
    __shared__ float h1s[64 * 128];
    __shared__ float w2s[16 * 128];
    __shared__ int srcs[64], dsts[64];
    __shared__ float es[64], w1e[128];

    int tid = threadIdx.x, tx = tid & 31, ty = tid >> 5;
    int e0 = blockIdx.x * 64;

    if (tid < 64) {
        srcs[tid] = ei[e0 + tid];
        dsts[tid] = ei[NE + e0 + tid];
        es[tid] = eattr[e0 + tid];
    }
    if (tid >= 128) w1e[tid - 128] = W1[((size_t)l * 129 + 128) * 128 + (tid - 128)];
    __syncthreads();

    // phase A: h1 = softplus(A[dst] + B[src] + e*w1e)   (b1 folded into A)
    #pragma unroll
    for (int it = 0; it < 32; ++it) {
        int idx = tid + it * 256;           // 8192
        int e = idx >> 7, c = idx & 127;
        float v = g_AB[(size_t)dsts[e] * 256 + c]
                + g_AB[(size_t)srcs[e] * 256 + 128 + c]
                + es[e] * w1e[c];
        h1s[e * 128 + c] = softplusf(v);
    }

    // phase B: m = softplus(h1 @ W2 + b2); atomic scatter to aggr[dst]
    float acc[8][4] = {};
    for (int k0 = 0; k0 < 128; k0 += 16) {
        __syncthreads();
        #pragma unroll
        for (int it = 0; it < 8; ++it) {
            int idx = tid + it * 256;       // 2048
            w2s[idx] = W2[((size_t)l * 128 + k0) * 128 + idx];
        }
        __syncthreads();
        #pragma unroll
        for (int kk = 0; kk < 16; ++kk) {
            float bv[4];
            #pragma unroll
            for (int j = 0; j < 4; ++j) bv[j] = w2s[kk * 128 + tx + 32 * j];
            #pragma unroll
            for (int i = 0; i < 8; ++i) {
                float a = h1s[(ty * 8 + i) * 128 + k0 + kk];
                #pragma unroll
                for (int j = 0; j < 4; ++j) acc[i][j] = fmaf(a, bv[j], acc[i][j]);
            }
        }
    }
    #pragma unroll
    for (int i = 0; i < 8; ++i) {
        int e = ty * 8 + i;
        int d = dsts[e];
        #pragma unroll
        for (int j = 0; j < 4; ++j) {
            int c = tx + 32 * j;
            float m = softplusf(acc[i][j] + b2[l * 128 + c]);
            atomicAdd(&g_aggr[(size_t)d * 128 + c], m);
        }
    }
}

// ---------------- k3: node MLP + residual + BN partial stats ----------------
// block = 256 threads, 32 nodes/block.
__global__ void __launch_bounds__(256) k3_node(int l, const float* __restrict__ W1,
                                               const float* __restrict__ b1,
                                               const float* __restrict__ W2,
                                               const float* __restrict__ b2) {
    __shared__ float hs[32 * 196];  // cols 0..63 = x, 64..191 = aggr then t
    __shared__ float ws[16 * 128];
    __shared__ float ssum[64], ssq[64];
    int tid = threadIdx.x, tx = tid & 31, ty = tid >> 5;
    int n0 = blockIdx.x * 32;

    if (tid < 64) { ssum[tid] = 0.0f; ssq[tid] = 0.0f; }
    for (int it = 0; it < 24; ++it) {
        int idx = tid + it * 256;           // 6144
        int i = idx / 192, c = idx - i * 192;
        int node = n0 + i;
        float v = 0.0f;
        if (node < NN) v = (c < 64) ? g_x[(size_t)node * DD + c]
                                    : g_aggr[(size_t)node * HH + (c - 64)];
        hs[i * 196 + c] = v;
    }
    __syncthreads();

    // GEMM1: t = softplus([x|aggr] @ nW1 + b1), K=192
    float acc[4][4] = {};
    for (int k0 = 0; k0 < 192; k0 += 16) {
        if (k0) __syncthreads();
        #pragma unroll
        for (int it = 0; it < 8; ++it) {
            int idx = tid + it * 256;       // 2048
            ws[idx] = W1[((size_t)l * 192 + k0) * 128 + idx];
        }
        __syncthreads();
        #pragma unroll
        for (int kk = 0; kk < 16; ++kk) {
            float bv[4];
            #pragma unroll
            for (int j = 0; j < 4; ++j) bv[j] = ws[kk * 128 + tx + 32 * j];
            #pragma unroll
            for (int i = 0; i < 4; ++i) {
                float a = hs[(ty * 4 + i) * 196 + k0 + kk];
                #pragma unroll
                for (int j = 0; j < 4; ++j) acc[i][j] = fmaf(a, bv[j], acc[i][j]);
            }
        }
    }
    __syncthreads();   // all aggr reads done; overwrite cols 64..191 with t
    #pragma unroll
    for (int i = 0; i < 4; ++i)
        #pragma unroll
        for (int j = 0; j < 4; ++j) {
            int c = tx + 32 * j;
            hs[(ty * 4 + i) * 196 + 64 + c] = softplusf(acc[i][j] + b1[l * 128 + c]);
        }
    __syncthreads();

    // GEMM2: y = t @ nW2 + b2 + x, K=128, 64 cols
    float acc2[4][2] = {};
    for (int k0 = 0; k0 < 128; k0 += 16) {
        __syncthreads();
        #pragma unroll
        for (int it = 0; it < 4; ++it) {
            int idx = tid + it * 256;       // 1024
            ws[idx] = W2[((size_t)l * 128 + k0) * 64 + idx];
        }
        __syncthreads();
        #pragma unroll
        for (int kk = 0; kk < 16; ++kk) {
            float bv0 = ws[kk * 64 + tx];
            float bv1 = ws[kk * 64 + tx + 32];
            #pragma unroll
            for (int i = 0; i < 4; ++i) {
                float a = hs[(ty * 4 + i) * 196 + 64 + k0 + kk];
                acc2[i][0] = fmaf(a, bv0, acc2[i][0]);
                acc2[i][1] = fmaf(a, bv1, acc2[i][1]);
            }
        }
    }
    float s1[2] = {0, 0}, s2[2] = {0, 0};
    #pragma unroll
    for (int i = 0; i < 4; ++i) {
        int node = n0 + ty * 4 + i;
        if (node < NN) {
            #pragma unroll
            for (int j = 0; j < 2; ++j) {
                int c = tx + 32 * j;
                float y = acc2[i][j] + b2[l * 64 + c] + hs[(ty * 4 + i) * 196 + c];
                g_x[(size_t)node * DD + c] = y;
                s1[j] += y;
                s2[j] += y * y;
            }
        }
    }
    atomicAdd(&ssum[tx], s1[0]); atomicAdd(&ssum[tx + 32], s1[1]);
    atomicAdd(&ssq[tx],  s2[0]); atomicAdd(&ssq[tx + 32],  s2[1]);
    __syncthreads();
    if (tid < 64) {
        atomicAdd(&g_stats[tid], ssum[tid]);
        atomicAdd(&g_stats[64 + tid], ssq[tid]);
    }
}

// ---------------- k4: batchnorm normalize (in place) ----------------
__global__ void k4_bn(int l, const float* __restrict__ gamma, const float* __restrict__ beta) {
    int idx = blockIdx.x * blockDim.x + threadIdx.x;
    if (idx >= NN * DD) return;
    int c = idx & 63;
    const float invN = 1.0f / (float)NN;
    float mu = g_stats[c] * invN;
    float var = g_stats[64 + c] * invN - mu * mu;
    float inv = rsqrtf(var + 1e-5f);
    float v = g_x[idx];
    g_x[idx] = gamma[l * 64 + c] * (v - mu) * inv + beta[l * 64 + c];
}

// ---------------- k5: global mean pool (atomic scatter) ----------------
__global__ void k5_pool(const int* __restrict__ batch) {
    int idx = blockIdx.x * blockDim.x + threadIdx.x;
    if (idx >= NN * DD) return;
    int i = idx >> 6, c = idx & 63;
    int b = batch[i];
    atomicAdd(&g_pool[b * DD + c], g_x[idx]);
    if (c == 0) atomicAdd(&g_cnt[b], 1.0f);
}

// ---------------- k6: output MLP, one block per graph ----------------
__global__ void k6_out(const float* __restrict__ W1, const float* __restrict__ b1,
                       const float* __restrict__ W2, const float* __restrict__ b2,
                       float* __restrict__ out) {
    __shared__ float p[64];
    __shared__ float red[128];
    int g = blockIdx.x, c = threadIdx.x;   // 128 threads
    if (c < 64) p[c] = g_pool[g * DD + c] / fmaxf(g_cnt[g], 1.0f);
    __syncthreads();
    float acc = b1[c];
    #pragma unroll
    for (int d = 0; d < 64; ++d) acc = fmaf(p[d], W1[d * 128 + c], acc);
    red[c] = softplusf(acc) * W2[c];
    __syncthreads();
    for (int s = 64; s > 0; s >>= 1) {
        if (c < s) red[c] += red[c + s];
        __syncthreads();
    }
    if (c == 0) out[g] = red[0] + b2[0];
}

// ---------------- launcher ----------------
extern "C" void kernel_launch(void* const* d_in, const int* in_sizes, int n_in,
                              void* d_out, int out_size) {
    const int*   atom_z = (const int*)  d_in[0];
    const int*   ei     = (const int*)  d_in[1];
    const float* eattr  = (const float*)d_in[2];
    const int*   batch  = (const int*)  d_in[3];
    const float* emb    = (const float*)d_in[4];
    const float* eW1    = (const float*)d_in[5];
    const float* eb1    = (const float*)d_in[6];
    const float* eW2    = (const float*)d_in[7];
    const float* eb2    = (const float*)d_in[8];
    const float* nW1    = (const float*)d_in[9];
    const float* nb1    = (const float*)d_in[10];
    const float* nW2    = (const float*)d_in[11];
    const float* nb2    = (const float*)d_in[12];
    const float* bng    = (const float*)d_in[13];
    const float* bnb    = (const float*)d_in[14];
    const float* oW1    = (const float*)d_in[15];
    const float* ob1    = (const float*)d_in[16];
    const float* oW2    = (const float*)d_in[17];
    const float* ob2    = (const float*)d_in[18];
    float* out = (float*)d_out;

    k0_embed<<<(NN * DD + 255) / 256, 256>>>(atom_z, emb);
    for (int l = 0; l < NL; ++l) {
        kzero_layer<<<(NN * HH + 255) / 256, 256>>>();
        k1_AB<<<dim3((NN + 63) / 64, 2), 256>>>(l, eW1, eb1);
        k2_edge<<<NE / 64, 256>>>(l, ei, eattr, eW1, eW2, eb2);
        k3_node<<<(NN + 31) / 32, 256>>>(l, nW1, nb1, nW2, nb2);
        k4_bn<<<(NN * DD + 255) / 256, 256>>>(l, bng, bnb);
    }
    kzero_pool<<<(GG * DD + 255) / 256, 256>>>();
    k5_pool<<<(NN * DD + 255) / 256, 256>>>(batch);
    k6_out<<<GG, 128>>>(oW1, ob1, oW2, ob2, out);
}

// round 2
// speedup vs baseline: 1.7308x; 1.7308x over previous
#include <cuda_runtime.h>
#include <math.h>

#define NN 50000
#define NE 800000
#define DD 64
#define HH 128
#define GG 128
#define NL 3

// ---------------- device scratch ----------------
__device__ float g_x[NN * DD];
__device__ float g_AB[(size_t)NN * 256];   // [A=x@W1a+b1 | B=x@W1b]
__device__ float g_aggr[(size_t)NN * HH];
__device__ float g_stats[2 * DD];
__device__ float g_pool[GG * DD];
__device__ float g_cnt[GG];
__device__ int   g_hist[NN];               // cursor for counting sort
__device__ int   g_perm[NE];               // edges sorted by dst

__device__ __forceinline__ float softplusf(float x) {
    return fmaxf(x, 0.0f) + __logf(1.0f + __expf(-fabsf(x)));
}
__device__ __forceinline__ unsigned to_tf32(float x) {
    unsigned u;
    asm("cvt.rna.tf32.f32 %0, %1;" : "=r"(u) : "f"(x));
    return u;
}

// ---------------- k0: embedding gather ----------------
__global__ void k0_embed(const int* __restrict__ az, const float* __restrict__ emb) {
    int idx = blockIdx.x * blockDim.x + threadIdx.x;
    if (idx >= NN * DD) return;
    int i = idx >> 6, c = idx & 63;
    g_x[idx] = emb[az[i] * DD + c];
}

// ---------------- sort-by-dst (counting sort) ----------------
__global__ void kz_hist() {
    int i = blockIdx.x * blockDim.x + threadIdx.x;
    if (i < NN) g_hist[i] = 0;
}
__global__ void k_hist(const int* __restrict__ ei) {
    int e = blockIdx.x * blockDim.x + threadIdx.x;
    if (e < NE) atomicAdd(&g_hist[ei[NE + e]], 1);
}
__global__ void k_scan() {   // 1 block, 1024 threads: exclusive scan -> cursor in g_hist
    __shared__ int s[1024];
    int tid = threadIdx.x;
    int carry = 0;
    for (int base = 0; base < NN; base += 1024) {
        int i = base + tid;
        int v = (i < NN) ? g_hist[i] : 0;
        s[tid] = v;
        __syncthreads();
        for (int off = 1; off < 1024; off <<= 1) {
            int t = (tid >= off) ? s[tid - off] : 0;
            __syncthreads();
            s[tid] += t;
            __syncthreads();
        }
        if (i < NN) g_hist[i] = carry + s[tid] - v;   // exclusive
        carry += s[1023];
        __syncthreads();
    }
}
__global__ void k_scatter(const int* __restrict__ ei) {
    int e = blockIdx.x * blockDim.x + threadIdx.x;
    if (e >= NE) return;
    int d = ei[NE + e];
    int pos = atomicAdd(&g_hist[d], 1);
    g_perm[pos] = e;
}

// ---------------- zero kernels ----------------
__global__ void kzero_layer() {
    int i = blockIdx.x * blockDim.x + threadIdx.x;
    if (i < NN * HH) g_aggr[i] = 0.0f;
    if (i < 2 * DD) g_stats[i] = 0.0f;
}
__global__ void kzero_pool() {
    int i = blockIdx.x * blockDim.x + threadIdx.x;
    if (i < GG * DD) g_pool[i] = 0.0f;
    if (i < GG) g_cnt[i] = 0.0f;
}

// ---------------- k1: AB = x @ [W1a | W1b]  (A gets +b1) ----------------
__global__ void __launch_bounds__(256) k1_AB(int l, const float* __restrict__ W1,
                                             const float* __restrict__ b1) {
    __shared__ float xs[64 * 64];
    __shared__ float ws[32 * 128];
    int tid = threadIdx.x, tx = tid & 31, ty = tid >> 5;
    int n0 = blockIdx.x * 64;
    int half = blockIdx.y;

    for (int it = 0; it < 16; ++it) {
        int idx = tid + it * 256;
        int i = idx >> 6, c = idx & 63;
        int node = n0 + i;
        xs[idx] = (node < NN) ? g_x[(size_t)node * DD + c] : 0.0f;
    }
    const float* Wp = W1 + ((size_t)l * 129 + half * 64) * 128;

    float acc[8][4] = {};
    for (int kc = 0; kc < 64; kc += 32) {
        __syncthreads();
        for (int it = 0; it < 16; ++it) {
            int idx = tid + it * 256;
            ws[idx] = Wp[(size_t)kc * 128 + idx];
        }
        __syncthreads();
        #pragma unroll 8
        for (int k = 0; k < 32; ++k) {
            float bv[4];
            #pragma unroll
            for (int j = 0; j < 4; ++j) bv[j] = ws[k * 128 + tx + 32 * j];
            #pragma unroll
            for (int i = 0; i < 8; ++i) {
                float a = xs[(ty * 8 + i) * 64 + kc + k];
                #pragma unroll
                for (int j = 0; j < 4; ++j) acc[i][j] = fmaf(a, bv[j], acc[i][j]);
            }
        }
    }
    #pragma unroll
    for (int i = 0; i < 8; ++i) {
        int node = n0 + ty * 8 + i;
        if (node < NN) {
            #pragma unroll
            for (int j = 0; j < 4; ++j) {
                int c = tx + 32 * j;
                float v = acc[i][j];
                if (half == 0) v += b1[l * 128 + c];
                g_AB[(size_t)node * 256 + half * 128 + c] = v;
            }
        }
    }
}

// ---------------- k2: edge MLP, tf32 tensor cores + segmented reduce ----------------
// 256 threads = 8 warps; 64 edges/block (sorted by dst); N=128, K=128.
#define H1P 132
#define W2P 20
__global__ void __launch_bounds__(256) k2_edge(int l, const int* __restrict__ ei,
                                               const float* __restrict__ eattr,
                                               const float* __restrict__ W1,
                                               const float* __restrict__ W2,
                                               const float* __restrict__ b2) {
    __shared__ unsigned h1s[64 * H1P];   // tf32 h1, later fp32 m
    __shared__ unsigned w2s[128 * W2P];  // W2 chunk, transposed [n][k], tf32
    __shared__ int srcs[64], dsts[64];
    __shared__ float es[64];
    __shared__ float4 w1e4[32];
    __shared__ float b2s[128];

    int tid = threadIdx.x;
    int e0 = blockIdx.x * 64;

    if (tid < 64) {
        int e = g_perm[e0 + tid];
        srcs[tid] = ei[e];
        dsts[tid] = ei[NE + e];
        es[tid] = eattr[e];
    } else if (tid < 192) {
        int c = tid - 64;
        ((float*)w1e4)[c] = W1[((size_t)l * 129 + 128) * 128 + c];
    } else {
        // nothing
    }
    if (tid < 128) b2s[tid] = b2[l * 128 + tid];
    __syncthreads();

    // phase A: h1 = softplus(A[dst] + B[src] + e*w1e), store tf32
    const float4* AB4 = (const float4*)g_AB;  // 64 float4 per node row
    #pragma unroll
    for (int it = 0; it < 8; ++it) {
        int idx = tid + it * 256;            // 2048
        int e = idx >> 5, q = idx & 31;
        float4 a = AB4[(size_t)dsts[e] * 64 + q];
        float4 b = AB4[(size_t)srcs[e] * 64 + 32 + q];
        float ev = es[e];
        float4 w = w1e4[q];
        unsigned* o = &h1s[e * H1P + q * 4];
        o[0] = to_tf32(softplusf(a.x + b.x + ev * w.x));
        o[1] = to_tf32(softplusf(a.y + b.y + ev * w.y));
        o[2] = to_tf32(softplusf(a.z + b.z + ev * w.z));
        o[3] = to_tf32(softplusf(a.w + b.w + ev * w.w));
    }

    // phase B: D = h1 @ W2 via mma.sync tf32
    int warp = tid >> 5, lane = tid & 31;
    int mb = (warp & 3) * 16;       // edge-row base
    int nb = (warp >> 2) * 64;      // col base
    int g = lane >> 2, tg = lane & 3;

    float acc[8][4] = {};
    for (int k0 = 0; k0 < 128; k0 += 16) {
        __syncthreads();
        #pragma unroll
        for (int it = 0; it < 8; ++it) {
            int idx = tid + it * 256;        // 2048
            int col = idx & 127, kk = idx >> 7;
            w2s[col * W2P + kk] = to_tf32(W2[((size_t)l * 128 + k0 + kk) * 128 + col]);
        }
        __syncthreads();
        #pragma unroll
        for (int ks = 0; ks < 16; ks += 8) {
            unsigned a0 = h1s[(mb + g) * H1P + k0 + ks + tg];
            unsigned a1 = h1s[(mb + g + 8) * H1P + k0 + ks + tg];
            unsigned a2 = h1s[(mb + g) * H1P + k0 + ks + tg + 4];
            unsigned a3 = h1s[(mb + g + 8) * H1P + k0 + ks + tg + 4];
            #pragma unroll
            for (int nt = 0; nt < 8; ++nt) {
                unsigned b0 = w2s[(nb + nt * 8 + g) * W2P + ks + tg];
                unsigned b1 = w2s[(nb + nt * 8 + g) * W2P + ks + tg + 4];
                asm volatile(
                    "mma.sync.aligned.m16n8k8.row.col.f32.tf32.tf32.f32 "
                    "{%0,%1,%2,%3}, {%4,%5,%6,%7}, {%8,%9}, {%0,%1,%2,%3};"
                    : "+f"(acc[nt][0]), "+f"(acc[nt][1]), "+f"(acc[nt][2]), "+f"(acc[nt][3])
                    : "r"(a0), "r"(a1), "r"(a2), "r"(a3), "r"(b0), "r"(b1));
            }
        }
    }

    // m = softplus(D + b2) -> smem (reuse h1s as float)
    __syncthreads();
    float* mf = (float*)h1s;
    #pragma unroll
    for (int nt = 0; nt < 8; ++nt) {
        int c0 = nb + nt * 8 + 2 * tg;
        mf[(mb + g) * H1P + c0]     = softplusf(acc[nt][0] + b2s[c0]);
        mf[(mb + g) * H1P + c0 + 1] = softplusf(acc[nt][1] + b2s[c0 + 1]);
        mf[(mb + g + 8) * H1P + c0]     = softplusf(acc[nt][2] + b2s[c0]);
        mf[(mb + g + 8) * H1P + c0 + 1] = softplusf(acc[nt][3] + b2s[c0 + 1]);
    }
    __syncthreads();

    // segmented reduction over sorted dst runs; one atomic per run per column
    int c = tid & 127;
    int r0 = (tid >> 7) * 32;
    float racc = 0.0f;
    int prev = dsts[r0];
    #pragma unroll 4
    for (int r = r0; r < r0 + 32; ++r) {
        int d = dsts[r];
        if (d != prev) {
            atomicAdd(&g_aggr[(size_t)prev * 128 + c], racc);
            racc = 0.0f;
            prev = d;
        }
        racc += mf[r * H1P + c];
    }
    atomicAdd(&g_aggr[(size_t)prev * 128 + c], racc);
}

// ---------------- k3: node MLP + residual + BN partial stats ----------------
__global__ void __launch_bounds__(256) k3_node(int l, const float* __restrict__ W1,
                                               const float* __restrict__ b1,
                                               const float* __restrict__ W2,
                                               const float* __restrict__ b2) {
    __shared__ float hs[32 * 196];
    __shared__ float ws[16 * 128];
    __shared__ float ssum[64], ssq[64];
    int tid = threadIdx.x, tx = tid & 31, ty = tid >> 5;
    int n0 = blockIdx.x * 32;

    if (tid < 64) { ssum[tid] = 0.0f; ssq[tid] = 0.0f; }
    for (int it = 0; it < 24; ++it) {
        int idx = tid + it * 256;
        int i = idx / 192, c = idx - i * 192;
        int node = n0 + i;
        float v = 0.0f;
        if (node < NN) v = (c < 64) ? g_x[(size_t)node * DD + c]
                                    : g_aggr[(size_t)node * HH + (c - 64)];
        hs[i * 196 + c] = v;
    }
    __syncthreads();

    float acc[4][4] = {};
    for (int k0 = 0; k0 < 192; k0 += 16) {
        if (k0) __syncthreads();
        #pragma unroll
        for (int it = 0; it < 8; ++it) {
            int idx = tid + it * 256;
            ws[idx] = W1[((size_t)l * 192 + k0) * 128 + idx];
        }
        __syncthreads();
        #pragma unroll
        for (int kk = 0; kk < 16; ++kk) {
            float bv[4];
            #pragma unroll
            for (int j = 0; j < 4; ++j) bv[j] = ws[kk * 128 + tx + 32 * j];
            #pragma unroll
            for (int i = 0; i < 4; ++i) {
                float a = hs[(ty * 4 + i) * 196 + k0 + kk];
                #pragma unroll
                for (int j = 0; j < 4; ++j) acc[i][j] = fmaf(a, bv[j], acc[i][j]);
            }
        }
    }
    __syncthreads();
    #pragma unroll
    for (int i = 0; i < 4; ++i)
        #pragma unroll
        for (int j = 0; j < 4; ++j) {
            int c = tx + 32 * j;
            hs[(ty * 4 + i) * 196 + 64 + c] = softplusf(acc[i][j] + b1[l * 128 + c]);
        }
    __syncthreads();

    float acc2[4][2] = {};
    for (int k0 = 0; k0 < 128; k0 += 16) {
        __syncthreads();
        #pragma unroll
        for (int it = 0; it < 4; ++it) {
            int idx = tid + it * 256;
            ws[idx] = W2[((size_t)l * 128 + k0) * 64 + idx];
        }
        __syncthreads();
        #pragma unroll
        for (int kk = 0; kk < 16; ++kk) {
            float bv0 = ws[kk * 64 + tx];
            float bv1 = ws[kk * 64 + tx + 32];
            #pragma unroll
            for (int i = 0; i < 4; ++i) {
                float a = hs[(ty * 4 + i) * 196 + 64 + k0 + kk];
                acc2[i][0] = fmaf(a, bv0, acc2[i][0]);
                acc2[i][1] = fmaf(a, bv1, acc2[i][1]);
            }
        }
    }
    float s1[2] = {0, 0}, s2[2] = {0, 0};
    #pragma unroll
    for (int i = 0; i < 4; ++i) {
        int node = n0 + ty * 4 + i;
        if (node < NN) {
            #pragma unroll
            for (int j = 0; j < 2; ++j) {
                int c = tx + 32 * j;
                float y = acc2[i][j] + b2[l * 64 + c] + hs[(ty * 4 + i) * 196 + c];
                g_x[(size_t)node * DD + c] = y;
                s1[j] += y;
                s2[j] += y * y;
            }
        }
    }
    atomicAdd(&ssum[tx], s1[0]); atomicAdd(&ssum[tx + 32], s1[1]);
    atomicAdd(&ssq[tx],  s2[0]); atomicAdd(&ssq[tx + 32],  s2[1]);
    __syncthreads();
    if (tid < 64) {
        atomicAdd(&g_stats[tid], ssum[tid]);
        atomicAdd(&g_stats[64 + tid], ssq[tid]);
    }
}

// ---------------- k4: batchnorm normalize ----------------
__global__ void k4_bn(int l, const float* __restrict__ gamma, const float* __restrict__ beta) {
    int idx = blockIdx.x * blockDim.x + threadIdx.x;
    if (idx >= NN * DD) return;
    int c = idx & 63;
    const float invN = 1.0f / (float)NN;
    float mu = g_stats[c] * invN;
    float var = g_stats[64 + c] * invN - mu * mu;
    float inv = rsqrtf(var + 1e-5f);
    float v = g_x[idx];
    g_x[idx] = gamma[l * 64 + c] * (v - mu) * inv + beta[l * 64 + c];
}

// ---------------- k5: global mean pool ----------------
__global__ void k5_pool(const int* __restrict__ batch) {
    int idx = blockIdx.x * blockDim.x + threadIdx.x;
    if (idx >= NN * DD) return;
    int i = idx >> 6, c = idx & 63;
    int b = batch[i];
    atomicAdd(&g_pool[b * DD + c], g_x[idx]);
    if (c == 0) atomicAdd(&g_cnt[b], 1.0f);
}

// ---------------- k6: output MLP ----------------
__global__ void k6_out(const float* __restrict__ W1, const float* __restrict__ b1,
                       const float* __restrict__ W2, const float* __restrict__ b2,
                       float* __restrict__ out) {
    __shared__ float p[64];
    __shared__ float red[128];
    int g = blockIdx.x, c = threadIdx.x;
    if (c < 64) p[c] = g_pool[g * DD + c] / fmaxf(g_cnt[g], 1.0f);
    __syncthreads();
    float acc = b1[c];
    #pragma unroll
    for (int d = 0; d < 64; ++d) acc = fmaf(p[d], W1[d * 128 + c], acc);
    red[c] = softplusf(acc) * W2[c];
    __syncthreads();
    for (int s = 64; s > 0; s >>= 1) {
        if (c < s) red[c] += red[c + s];
        __syncthreads();
    }
    if (c == 0) out[g] = red[0] + b2[0];
}

// ---------------- launcher ----------------
extern "C" void kernel_launch(void* const* d_in, const int* in_sizes, int n_in,
                              void* d_out, int out_size) {
    const int*   atom_z = (const int*)  d_in[0];
    const int*   ei     = (const int*)  d_in[1];
    const float* eattr  = (const float*)d_in[2];
    const int*   batch  = (const int*)  d_in[3];
    const float* emb    = (const float*)d_in[4];
    const float* eW1    = (const float*)d_in[5];
    const float* eb1    = (const float*)d_in[6];
    const float* eW2    = (const float*)d_in[7];
    const float* eb2    = (const float*)d_in[8];
    const float* nW1    = (const float*)d_in[9];
    const float* nb1    = (const float*)d_in[10];
    const float* nW2    = (const float*)d_in[11];
    const float* nb2    = (const float*)d_in[12];
    const float* bng    = (const float*)d_in[13];
    const float* bnb    = (const float*)d_in[14];
    const float* oW1    = (const float*)d_in[15];
    const float* ob1    = (const float*)d_in[16];
    const float* oW2    = (const float*)d_in[17];
    const float* ob2    = (const float*)d_in[18];
    float* out = (float*)d_out;

    k0_embed<<<(NN * DD + 255) / 256, 256>>>(atom_z, emb);

    // counting sort of edges by dst
    kz_hist<<<(NN + 255) / 256, 256>>>();
    k_hist<<<(NE + 255) / 256, 256>>>(ei);
    k_scan<<<1, 1024>>>();
    k_scatter<<<(NE + 255) / 256, 256>>>(ei);

    for (int l = 0; l < NL; ++l) {
        kzero_layer<<<(NN * HH + 255) / 256, 256>>>();
        k1_AB<<<dim3((NN + 63) / 64, 2), 256>>>(l, eW1, eb1);
        k2_edge<<<NE / 64, 256>>>(l, ei, eattr, eW1, eW2, eb2);
        k3_node<<<(NN + 31) / 32, 256>>>(l, nW1, nb1, nW2, nb2);
        k4_bn<<<(NN * DD + 255) / 256, 256>>>(l, bng, bnb);
    }
    kzero_pool<<<(GG * DD + 255) / 256, 256>>>();
    k5_pool<<<(NN * DD + 255) / 256, 256>>>(batch);
    k6_out<<<GG, 128>>>(oW1, ob1, oW2, ob2, out);
}

// round 3
// speedup vs baseline: 1.9169x; 1.1075x over previous
#include <cuda_runtime.h>
#include <math.h>

#define NN 50000
#define NE 800000
#define DD 64
#define HH 128
#define GG 128
#define NL 3

// ---------------- device scratch ----------------
__device__ float g_x[NN * DD];
__device__ float g_AB[(size_t)NN * 256];   // [A=x@W1a+b1 | B=x@W1b]
__device__ float g_aggr[(size_t)NN * HH];
__device__ float g_stats[2 * DD];
__device__ float g_pool[GG * DD];
__device__ float g_cnt[GG];
__device__ int   g_hist[NN];
__device__ int   g_bsum[64];
__device__ int   g_perm[NE];

__device__ __forceinline__ float softplusf(float x) {
    return fmaxf(x, 0.0f) + __logf(1.0f + __expf(-fabsf(x)));
}
__device__ __forceinline__ unsigned to_tf32(float x) {
    unsigned u;
    asm("cvt.rna.tf32.f32 %0, %1;" : "=r"(u) : "f"(x));
    return u;
}
__device__ __forceinline__ void mma8(float* c, unsigned a0, unsigned a1,
                                     unsigned a2, unsigned a3,
                                     unsigned b0, unsigned b1) {
    asm volatile(
        "mma.sync.aligned.m16n8k8.row.col.f32.tf32.tf32.f32 "
        "{%0,%1,%2,%3}, {%4,%5,%6,%7}, {%8,%9}, {%0,%1,%2,%3};"
        : "+f"(c[0]), "+f"(c[1]), "+f"(c[2]), "+f"(c[3])
        : "r"(a0), "r"(a1), "r"(a2), "r"(a3), "r"(b0), "r"(b1));
}

// ---------------- k0: embedding gather ----------------
__global__ void k0_embed(const int* __restrict__ az, const float* __restrict__ emb) {
    int idx = blockIdx.x * blockDim.x + threadIdx.x;
    if (idx >= NN * DD) return;
    int i = idx >> 6, c = idx & 63;
    g_x[idx] = emb[az[i] * DD + c];
}

// ---------------- counting sort of edges by dst ----------------
__global__ void kz_hist() {
    int i = blockIdx.x * blockDim.x + threadIdx.x;
    if (i < NN) g_hist[i] = 0;
}
__global__ void k_hist(const int* __restrict__ ei) {
    int e = blockIdx.x * blockDim.x + threadIdx.x;
    if (e < NE) atomicAdd(&g_hist[ei[NE + e]], 1);
}
__global__ void k_scan_part() {   // blocks of 1024, warp-shuffle scan
    __shared__ int wsum[32];
    int tid = threadIdx.x, lane = tid & 31, wid = tid >> 5;
    int i = blockIdx.x * 1024 + tid;
    int v = (i < NN) ? g_hist[i] : 0;
    int x = v;
    #pragma unroll
    for (int off = 1; off < 32; off <<= 1) {
        int y = __shfl_up_sync(0xffffffffu, x, off);
        if (lane >= off) x += y;
    }
    if (lane == 31) wsum[wid] = x;
    __syncthreads();
    if (wid == 0) {
        int s = wsum[lane];
        #pragma unroll
        for (int off = 1; off < 32; off <<= 1) {
            int y = __shfl_up_sync(0xffffffffu, s, off);
            if (lane >= off) s += y;
        }
        wsum[lane] = s;
    }
    __syncthreads();
    int woff = (wid > 0) ? wsum[wid - 1] : 0;
    if (i < NN) g_hist[i] = x - v + woff;      // exclusive within block
    if (tid == 1023) g_bsum[blockIdx.x] = x + woff;  // block total
}
__global__ void k_scan_top() {    // 1 block, 64 threads
    __shared__ int s[64];
    int tid = threadIdx.x;
    int nb = (NN + 1023) / 1024;
    int v = (tid < nb) ? g_bsum[tid] : 0;
    s[tid] = v;
    __syncthreads();
    for (int off = 1; off < 64; off <<= 1) {
        int t = (tid >= off) ? s[tid - off] : 0;
        __syncthreads();
        s[tid] += t;
        __syncthreads();
    }
    if (tid < nb) g_bsum[tid] = s[tid] - v;   // exclusive
}
__global__ void k_scan_add() {
    int i = blockIdx.x * 1024 + threadIdx.x;
    if (i < NN) g_hist[i] += g_bsum[blockIdx.x];
}
__global__ void k_scatter(const int* __restrict__ ei) {
    int e = blockIdx.x * blockDim.x + threadIdx.x;
    if (e >= NE) return;
    int d = ei[NE + e];
    int pos = atomicAdd(&g_hist[d], 1);
    g_perm[pos] = e;
}

// ---------------- zero kernels ----------------
__global__ void kzero_layer() {
    int i = blockIdx.x * blockDim.x + threadIdx.x;
    if (i < NN * HH) g_aggr[i] = 0.0f;
    if (i < 2 * DD) g_stats[i] = 0.0f;
}
__global__ void kzero_pool() {
    int i = blockIdx.x * blockDim.x + threadIdx.x;
    if (i < GG * DD) g_pool[i] = 0.0f;
    if (i < GG) g_cnt[i] = 0.0f;
}

// ---------------- k1: AB = x @ [W1a | W1b], tf32 mma ----------------
// 64 nodes/block, half in blockIdx.y: N=128, K=64.
__global__ void __launch_bounds__(256) k1_AB(int l, const float* __restrict__ W1,
                                             const float* __restrict__ b1) {
    __shared__ float xs[64 * 68];
    __shared__ unsigned ws[128 * 20];
    int tid = threadIdx.x, warp = tid >> 5, lane = tid & 31;
    int g = lane >> 2, tg = lane & 3;
    int n0 = blockIdx.x * 64;
    int half = blockIdx.y;
    int mb = (warp & 3) * 16, nb = (warp >> 2) * 64;

    #pragma unroll
    for (int it = 0; it < 16; ++it) {
        int idx = tid + it * 256;           // 4096
        int i = idx >> 6, c = idx & 63;
        int node = n0 + i;
        xs[i * 68 + c] = (node < NN) ? g_x[(size_t)node * DD + c] : 0.0f;
    }
    const float* Wp = W1 + ((size_t)l * 129 + half * 64) * 128;

    float acc[8][4] = {};
    for (int k0 = 0; k0 < 64; k0 += 16) {
        __syncthreads();
        #pragma unroll
        for (int it = 0; it < 8; ++it) {
            int idx = tid + it * 256;       // 2048
            int col = idx & 127, kk = idx >> 7;
            ws[col * 20 + kk] = to_tf32(Wp[(size_t)(k0 + kk) * 128 + col]);
        }
        __syncthreads();
        #pragma unroll
        for (int ks = 0; ks < 16; ks += 8) {
            unsigned a0 = to_tf32(xs[(mb + g) * 68 + k0 + ks + tg]);
            unsigned a1 = to_tf32(xs[(mb + g + 8) * 68 + k0 + ks + tg]);
            unsigned a2 = to_tf32(xs[(mb + g) * 68 + k0 + ks + tg + 4]);
            unsigned a3 = to_tf32(xs[(mb + g + 8) * 68 + k0 + ks + tg + 4]);
            #pragma unroll
            for (int nt = 0; nt < 8; ++nt) {
                unsigned b0 = ws[(nb + nt * 8 + g) * 20 + ks + tg];
                unsigned b1r = ws[(nb + nt * 8 + g) * 20 + ks + tg + 4];
                mma8(acc[nt], a0, a1, a2, a3, b0, b1r);
            }
        }
    }
    int row0 = n0 + mb + g, row1 = row0 + 8;
    #pragma unroll
    for (int nt = 0; nt < 8; ++nt) {
        int c0 = nb + nt * 8 + 2 * tg;
        float bb0 = (half == 0) ? b1[l * 128 + c0] : 0.0f;
        float bb1 = (half == 0) ? b1[l * 128 + c0 + 1] : 0.0f;
        if (row0 < NN) {
            g_AB[(size_t)row0 * 256 + half * 128 + c0]     = acc[nt][0] + bb0;
            g_AB[(size_t)row0 * 256 + half * 128 + c0 + 1] = acc[nt][1] + bb1;
        }
        if (row1 < NN) {
            g_AB[(size_t)row1 * 256 + half * 128 + c0]     = acc[nt][2] + bb0;
            g_AB[(size_t)row1 * 256 + half * 128 + c0 + 1] = acc[nt][3] + bb1;
        }
    }
}

// ---------------- k2: persistent edge MLP (tf32 mma, W2 resident) ----------------
// dynamic smem: w2s[128*132] u32 | h1s[64*132] u32 | srcs/dsts/es[64] | w1e[128] | b2s[128]
#define K2_GRID 296
__global__ void __launch_bounds__(256) k2_edge(int l, const int* __restrict__ ei,
                                               const float* __restrict__ eattr,
                                               const float* __restrict__ W1,
                                               const float* __restrict__ W2,
                                               const float* __restrict__ b2) {
    extern __shared__ unsigned sm[];
    unsigned* w2s = sm;                        // 16896
    unsigned* h1s = sm + 16896;                // 8448
    int* srcs = (int*)(sm + 25344);
    int* dsts = (int*)(sm + 25408);
    float* es = (float*)(sm + 25472);
    float* w1e = (float*)(sm + 25536);
    float* b2s = (float*)(sm + 25664);

    int tid = threadIdx.x, warp = tid >> 5, lane = tid & 31;
    int g = lane >> 2, tg = lane & 3;
    int mb = (warp & 3) * 16, nb = (warp >> 2) * 64;

    // stage W2 (tf32, [col][k] pitch 132) once
    #pragma unroll
    for (int it = 0; it < 64; ++it) {
        int idx = tid + it * 256;              // 16384
        int col = idx & 127, kk = idx >> 7;
        w2s[col * 132 + kk] = to_tf32(W2[((size_t)l * 128 + kk) * 128 + col]);
    }
    if (tid < 128) w1e[tid] = W1[((size_t)l * 129 + 128) * 128 + tid];
    else b2s[tid - 128] = b2[l * 128 + (tid - 128)];

    const float4* AB4 = (const float4*)g_AB;
    const float4* w1e4 = (const float4*)w1e;
    float* mf = (float*)h1s;

    for (int t = blockIdx.x; t < NE / 64; t += K2_GRID) {
        int e0 = t * 64;
        __syncthreads();                       // prev tile reduce done / W2 staged
        if (tid < 64) {
            int e = g_perm[e0 + tid];
            srcs[tid] = ei[e];
            dsts[tid] = ei[NE + e];
            es[tid] = eattr[e];
        }
        __syncthreads();

        // phase A: h1 = softplus(A[dst] + B[src] + e*w1e) -> tf32, STS.128
        #pragma unroll
        for (int it = 0; it < 8; ++it) {
            int idx = tid + it * 256;          // 2048
            int e = idx >> 5, q = idx & 31;
            float4 a = AB4[(size_t)dsts[e] * 64 + q];
            float4 b = AB4[(size_t)srcs[e] * 64 + 32 + q];
            float ev = es[e];
            float4 w = w1e4[q];
            uint4 r;
            r.x = to_tf32(softplusf(a.x + b.x + ev * w.x));
            r.y = to_tf32(softplusf(a.y + b.y + ev * w.y));
            r.z = to_tf32(softplusf(a.z + b.z + ev * w.z));
            r.w = to_tf32(softplusf(a.w + b.w + ev * w.w));
            *(uint4*)(h1s + e * 132 + q * 4) = r;
        }
        __syncthreads();

        // phase B: D = h1 @ W2
        float acc[8][4] = {};
        #pragma unroll
        for (int k0 = 0; k0 < 128; k0 += 8) {
            unsigned a0 = h1s[(mb + g) * 132 + k0 + tg];
            unsigned a1 = h1s[(mb + g + 8) * 132 + k0 + tg];
            unsigned a2 = h1s[(mb + g) * 132 + k0 + tg + 4];
            unsigned a3 = h1s[(mb + g + 8) * 132 + k0 + tg + 4];
            #pragma unroll
            for (int nt = 0; nt < 8; ++nt) {
                unsigned b0 = w2s[(nb + nt * 8 + g) * 132 + k0 + tg];
                unsigned b1r = w2s[(nb + nt * 8 + g) * 132 + k0 + tg + 4];
                mma8(acc[nt], a0, a1, a2, a3, b0, b1r);
            }
        }
        __syncthreads();                       // all A reads done before mf writes

        #pragma unroll
        for (int nt = 0; nt < 8; ++nt) {
            int c0 = nb + nt * 8 + 2 * tg;
            mf[(mb + g) * 132 + c0]         = softplusf(acc[nt][0] + b2s[c0]);
            mf[(mb + g) * 132 + c0 + 1]     = softplusf(acc[nt][1] + b2s[c0 + 1]);
            mf[(mb + g + 8) * 132 + c0]     = softplusf(acc[nt][2] + b2s[c0]);
            mf[(mb + g + 8) * 132 + c0 + 1] = softplusf(acc[nt][3] + b2s[c0 + 1]);
        }
        __syncthreads();

        // segmented reduction over sorted dst runs
        int c = tid & 127;
        int r0 = (tid >> 7) * 32;
        float racc = 0.0f;
        int prev = dsts[r0];
        #pragma unroll 4
        for (int r = r0; r < r0 + 32; ++r) {
            int d = dsts[r];
            if (d != prev) {
                atomicAdd(&g_aggr[(size_t)prev * 128 + c], racc);
                racc = 0.0f;
                prev = d;
            }
            racc += mf[r * 132 + c];
        }
        atomicAdd(&g_aggr[(size_t)prev * 128 + c], racc);
    }
}

// ---------------- k3: node MLP (GEMM1 tf32 mma) + residual + BN stats ----------------
__global__ void __launch_bounds__(256) k3_node(int l, const float* __restrict__ W1,
                                               const float* __restrict__ b1,
                                               const float* __restrict__ W2,
                                               const float* __restrict__ b2) {
    __shared__ float hs[32 * 196];
    __shared__ unsigned ws[128 * 20];          // also reused as float for GEMM2
    __shared__ float ssum[64], ssq[64];
    int tid = threadIdx.x, tx = tid & 31, ty = tid >> 5;
    int warp = ty, lane = tx, g = lane >> 2, tg = lane & 3;
    int mb = (warp & 1) * 16, nb = (warp >> 1) * 32;
    int n0 = blockIdx.x * 32;

    if (tid < 64) { ssum[tid] = 0.0f; ssq[tid] = 0.0f; }
    for (int it = 0; it < 24; ++it) {
        int idx = tid + it * 256;
        int i = idx / 192, c = idx - i * 192;
        int node = n0 + i;
        float v = 0.0f;
        if (node < NN) v = (c < 64) ? g_x[(size_t)node * DD + c]
                                    : g_aggr[(size_t)node * HH + (c - 64)];
        hs[i * 196 + c] = v;
    }

    // GEMM1: t = softplus([x|aggr] @ nW1 + b1), M=32, N=128, K=192 (tf32 mma)
    float acc[4][4] = {};
    for (int k0 = 0; k0 < 192; k0 += 16) {
        __syncthreads();
        #pragma unroll
        for (int it = 0; it < 8; ++it) {
            int idx = tid + it * 256;          // 2048
            int col = idx & 127, kk = idx >> 7;
            ws[col * 20 + kk] = to_tf32(W1[((size_t)l * 192 + k0 + kk) * 128 + col]);
        }
        __syncthreads();
        #pragma unroll
        for (int ks = 0; ks < 16; ks += 8) {
            unsigned a0 = to_tf32(hs[(mb + g) * 196 + k0 + ks + tg]);
            unsigned a1 = to_tf32(hs[(mb + g + 8) * 196 + k0 + ks + tg]);
            unsigned a2 = to_tf32(hs[(mb + g) * 196 + k0 + ks + tg + 4]);
            unsigned a3 = to_tf32(hs[(mb + g + 8) * 196 + k0 + ks + tg + 4]);
            #pragma unroll
            for (int nt = 0; nt < 4; ++nt) {
                unsigned b0 = ws[(nb + nt * 8 + g) * 20 + ks + tg];
                unsigned b1r = ws[(nb + nt * 8 + g) * 20 + ks + tg + 4];
                mma8(acc[nt], a0, a1, a2, a3, b0, b1r);
            }
        }
    }
    __syncthreads();
    #pragma unroll
    for (int nt = 0; nt < 4; ++nt) {
        int c0 = nb + nt * 8 + 2 * tg;
        hs[(mb + g) * 196 + 64 + c0]         = softplusf(acc[nt][0] + b1[l * 128 + c0]);
        hs[(mb + g) * 196 + 64 + c0 + 1]     = softplusf(acc[nt][1] + b1[l * 128 + c0 + 1]);
        hs[(mb + g + 8) * 196 + 64 + c0]     = softplusf(acc[nt][2] + b1[l * 128 + c0]);
        hs[(mb + g + 8) * 196 + 64 + c0 + 1] = softplusf(acc[nt][3] + b1[l * 128 + c0 + 1]);
    }

    // GEMM2: y = t @ nW2 + b2 + x (scalar fp32), K=128, 64 cols
    float* wf = (float*)ws;
    float acc2[4][2] = {};
    for (int k0 = 0; k0 < 128; k0 += 16) {
        __syncthreads();
        #pragma unroll
        for (int it = 0; it < 4; ++it) {
            int idx = tid + it * 256;          // 1024
            wf[idx] = W2[((size_t)l * 128 + k0) * 64 + idx];
        }
        __syncthreads();
        #pragma unroll
        for (int kk = 0; kk < 16; ++kk) {
            float bv0 = wf[kk * 64 + tx];
            float bv1 = wf[kk * 64 + tx + 32];
            #pragma unroll
            for (int i = 0; i < 4; ++i) {
                float a = hs[(ty * 4 + i) * 196 + 64 + k0 + kk];
                acc2[i][0] = fmaf(a, bv0, acc2[i][0]);
                acc2[i][1] = fmaf(a, bv1, acc2[i][1]);
            }
        }
    }
    float s1[2] = {0, 0}, s2[2] = {0, 0};
    #pragma unroll
    for (int i = 0; i < 4; ++i) {
        int node = n0 + ty * 4 + i;
        if (node < NN) {
            #pragma unroll
            for (int j = 0; j < 2; ++j) {
                int c = tx + 32 * j;
                float y = acc2[i][j] + b2[l * 64 + c] + hs[(ty * 4 + i) * 196 + c];
                g_x[(size_t)node * DD + c] = y;
                s1[j] += y;
                s2[j] += y * y;
            }
        }
    }
    atomicAdd(&ssum[tx], s1[0]); atomicAdd(&ssum[tx + 32], s1[1]);
    atomicAdd(&ssq[tx],  s2[0]); atomicAdd(&ssq[tx + 32],  s2[1]);
    __syncthreads();
    if (tid < 64) {
        atomicAdd(&g_stats[tid], ssum[tid]);
        atomicAdd(&g_stats[64 + tid], ssq[tid]);
    }
}

// ---------------- k4: batchnorm normalize ----------------
__global__ void k4_bn(int l, const float* __restrict__ gamma, const float* __restrict__ beta) {
    int idx = blockIdx.x * blockDim.x + threadIdx.x;
    if (idx >= NN * DD) return;
    int c = idx & 63;
    const float invN = 1.0f / (float)NN;
    float mu = g_stats[c] * invN;
    float var = g_stats[64 + c] * invN - mu * mu;
    float inv = rsqrtf(var + 1e-5f);
    float v = g_x[idx];
    g_x[idx] = gamma[l * 64 + c] * (v - mu) * inv + beta[l * 64 + c];
}

// ---------------- k5: global mean pool ----------------
__global__ void k5_pool(const int* __restrict__ batch) {
    int idx = blockIdx.x * blockDim.x + threadIdx.x;
    if (idx >= NN * DD) return;
    int i = idx >> 6, c = idx & 63;
    int b = batch[i];
    atomicAdd(&g_pool[b * DD + c], g_x[idx]);
    if (c == 0) atomicAdd(&g_cnt[b], 1.0f);
}

// ---------------- k6: output MLP ----------------
__global__ void k6_out(const float* __restrict__ W1, const float* __restrict__ b1,
                       const float* __restrict__ W2, const float* __restrict__ b2,
                       float* __restrict__ out) {
    __shared__ float p[64];
    __shared__ float red[128];
    int g = blockIdx.x, c = threadIdx.x;
    if (c < 64) p[c] = g_pool[g * DD + c] / fmaxf(g_cnt[g], 1.0f);
    __syncthreads();
    float acc = b1[c];
    #pragma unroll
    for (int d = 0; d < 64; ++d) acc = fmaf(p[d], W1[d * 128 + c], acc);
    red[c] = softplusf(acc) * W2[c];
    __syncthreads();
    for (int s = 64; s > 0; s >>= 1) {
        if (c < s) red[c] += red[c + s];
        __syncthreads();
    }
    if (c == 0) out[g] = red[0] + b2[0];
}

// ---------------- launcher ----------------
extern "C" void kernel_launch(void* const* d_in, const int* in_sizes, int n_in,
                              void* d_out, int out_size) {
    const int*   atom_z = (const int*)  d_in[0];
    const int*   ei     = (const int*)  d_in[1];
    const float* eattr  = (const float*)d_in[2];
    const int*   batch  = (const int*)  d_in[3];
    const float* emb    = (const float*)d_in[4];
    const float* eW1    = (const float*)d_in[5];
    const float* eb1    = (const float*)d_in[6];
    const float* eW2    = (const float*)d_in[7];
    const float* eb2    = (const float*)d_in[8];
    const float* nW1    = (const float*)d_in[9];
    const float* nb1    = (const float*)d_in[10];
    const float* nW2    = (const float*)d_in[11];
    const float* nb2    = (const float*)d_in[12];
    const float* bng    = (const float*)d_in[13];
    const float* bnb    = (const float*)d_in[14];
    const float* oW1    = (const float*)d_in[15];
    const float* ob1    = (const float*)d_in[16];
    const float* oW2    = (const float*)d_in[17];
    const float* ob2    = (const float*)d_in[18];
    float* out = (float*)d_out;

    const int K2_SMEM = 25792 * 4;   // 103168 B
    cudaFuncSetAttribute(k2_edge, cudaFuncAttributeMaxDynamicSharedMemorySize, K2_SMEM);

    k0_embed<<<(NN * DD + 255) / 256, 256>>>(atom_z, emb);

    kz_hist<<<(NN + 255) / 256, 256>>>();
    k_hist<<<(NE + 255) / 256, 256>>>(ei);
    int nsb = (NN + 1023) / 1024;
    k_scan_part<<<nsb, 1024>>>();
    k_scan_top<<<1, 64>>>();
    k_scan_add<<<nsb, 1024>>>();
    k_scatter<<<(NE + 255) / 256, 256>>>(ei);

    for (int l = 0; l < NL; ++l) {
        kzero_layer<<<(NN * HH + 255) / 256, 256>>>();
        k1_AB<<<dim3((NN + 63) / 64, 2), 256>>>(l, eW1, eb1);
        k2_edge<<<K2_GRID, 256, K2_SMEM>>>(l, ei, eattr, eW1, eW2, eb2);
        k3_node<<<(NN + 31) / 32, 256>>>(l, nW1, nb1, nW2, nb2);
        k4_bn<<<(NN * DD + 255) / 256, 256>>>(l, bng, bnb);
    }
    kzero_pool<<<(GG * DD + 255) / 256, 256>>>();
    k5_pool<<<(NN * DD + 255) / 256, 256>>>(batch);
    k6_out<<<GG, 128>>>(oW1, ob1, oW2, ob2, out);
}

// round 4
// speedup vs baseline: 2.4249x; 1.2650x over previous
#include <cuda_runtime.h>
#include <cuda_bf16.h>
#include <math.h>

#define NN 50000
#define NE 800000
#define DD 64
#define HH 128
#define GG 128
#define NL 3

// ---------------- device scratch ----------------
__device__ float g_x[NN * DD];
__device__ float g_AB[(size_t)NN * 256];   // [A=x@W1a+b1 | B=x@W1b]
__device__ float g_aggr[(size_t)NN * HH];
__device__ float g_stats[2 * DD];
__device__ float g_pool[GG * DD];
__device__ float g_cnt[GG];
__device__ int   g_hist[NN];
__device__ int   g_bsum[64];
__device__ int   g_perm[NE];

__device__ __forceinline__ float softplusf(float x) {
    return fmaxf(x, 0.0f) + __logf(1.0f + __expf(-fabsf(x)));
}
__device__ __forceinline__ unsigned to_tf32(float x) {
    unsigned u;
    asm("cvt.rna.tf32.f32 %0, %1;" : "=r"(u) : "f"(x));
    return u;
}
__device__ __forceinline__ unsigned pack_bf16(float lo, float hi) {
    unsigned r;
    asm("cvt.rn.bf16x2.f32 %0, %1, %2;" : "=r"(r) : "f"(hi), "f"(lo));
    return r;
}
__device__ __forceinline__ void mma8(float* c, unsigned a0, unsigned a1,
                                     unsigned a2, unsigned a3,
                                     unsigned b0, unsigned b1) {
    asm volatile(
        "mma.sync.aligned.m16n8k8.row.col.f32.tf32.tf32.f32 "
        "{%0,%1,%2,%3}, {%4,%5,%6,%7}, {%8,%9}, {%0,%1,%2,%3};"
        : "+f"(c[0]), "+f"(c[1]), "+f"(c[2]), "+f"(c[3])
        : "r"(a0), "r"(a1), "r"(a2), "r"(a3), "r"(b0), "r"(b1));
}
__device__ __forceinline__ void mma16bf(float* c, unsigned a0, unsigned a1,
                                        unsigned a2, unsigned a3,
                                        unsigned b0, unsigned b1) {
    asm volatile(
        "mma.sync.aligned.m16n8k16.row.col.f32.bf16.bf16.f32 "
        "{%0,%1,%2,%3}, {%4,%5,%6,%7}, {%8,%9}, {%0,%1,%2,%3};"
        : "+f"(c[0]), "+f"(c[1]), "+f"(c[2]), "+f"(c[3])
        : "r"(a0), "r"(a1), "r"(a2), "r"(a3), "r"(b0), "r"(b1));
}

// ---------------- k0: embedding gather ----------------
__global__ void k0_embed(const int* __restrict__ az, const float* __restrict__ emb) {
    int idx = blockIdx.x * blockDim.x + threadIdx.x;
    if (idx >= NN * DD) return;
    int i = idx >> 6, c = idx & 63;
    g_x[idx] = emb[az[i] * DD + c];
}

// ---------------- counting sort of edges by dst ----------------
__global__ void kz_hist() {
    int i = blockIdx.x * blockDim.x + threadIdx.x;
    if (i < NN) g_hist[i] = 0;
}
__global__ void k_hist(const int* __restrict__ ei) {
    int e = blockIdx.x * blockDim.x + threadIdx.x;
    if (e < NE) atomicAdd(&g_hist[ei[NE + e]], 1);
}
__global__ void k_scan_part() {
    __shared__ int wsum[32];
    int tid = threadIdx.x, lane = tid & 31, wid = tid >> 5;
    int i = blockIdx.x * 1024 + tid;
    int v = (i < NN) ? g_hist[i] : 0;
    int x = v;
    #pragma unroll
    for (int off = 1; off < 32; off <<= 1) {
        int y = __shfl_up_sync(0xffffffffu, x, off);
        if (lane >= off) x += y;
    }
    if (lane == 31) wsum[wid] = x;
    __syncthreads();
    if (wid == 0) {
        int s = wsum[lane];
        #pragma unroll
        for (int off = 1; off < 32; off <<= 1) {
            int y = __shfl_up_sync(0xffffffffu, s, off);
            if (lane >= off) s += y;
        }
        wsum[lane] = s;
    }
    __syncthreads();
    int woff = (wid > 0) ? wsum[wid - 1] : 0;
    if (i < NN) g_hist[i] = x - v + woff;
    if (tid == 1023) g_bsum[blockIdx.x] = x + woff;
}
__global__ void k_scan_top() {
    __shared__ int s[64];
    int tid = threadIdx.x;
    int nb = (NN + 1023) / 1024;
    int v = (tid < nb) ? g_bsum[tid] : 0;
    s[tid] = v;
    __syncthreads();
    for (int off = 1; off < 64; off <<= 1) {
        int t = (tid >= off) ? s[tid - off] : 0;
        __syncthreads();
        s[tid] += t;
        __syncthreads();
    }
    if (tid < nb) g_bsum[tid] = s[tid] - v;
}
__global__ void k_scan_add() {
    int i = blockIdx.x * 1024 + threadIdx.x;
    if (i < NN) g_hist[i] += g_bsum[blockIdx.x];
}
__global__ void k_scatter(const int* __restrict__ ei) {
    int e = blockIdx.x * blockDim.x + threadIdx.x;
    if (e >= NE) return;
    int d = ei[NE + e];
    int pos = atomicAdd(&g_hist[d], 1);
    g_perm[pos] = e;
}

// ---------------- zero kernels ----------------
__global__ void kzero_layer() {
    int i = blockIdx.x * blockDim.x + threadIdx.x;
    if (i < NN * HH) g_aggr[i] = 0.0f;
    if (i < 2 * DD) g_stats[i] = 0.0f;
}
__global__ void kzero_pool() {
    int i = blockIdx.x * blockDim.x + threadIdx.x;
    if (i < GG * DD) g_pool[i] = 0.0f;
    if (i < GG) g_cnt[i] = 0.0f;
}

// ---------------- k1: AB = x @ [W1a | W1b], tf32 mma ----------------
__global__ void __launch_bounds__(256) k1_AB(int l, const float* __restrict__ W1,
                                             const float* __restrict__ b1) {
    __shared__ float xs[64 * 68];
    __shared__ unsigned ws[128 * 20];
    int tid = threadIdx.x, warp = tid >> 5, lane = tid & 31;
    int g = lane >> 2, tg = lane & 3;
    int n0 = blockIdx.x * 64;
    int half = blockIdx.y;
    int mb = (warp & 3) * 16, nb = (warp >> 2) * 64;

    #pragma unroll
    for (int it = 0; it < 16; ++it) {
        int idx = tid + it * 256;
        int i = idx >> 6, c = idx & 63;
        int node = n0 + i;
        xs[i * 68 + c] = (node < NN) ? g_x[(size_t)node * DD + c] : 0.0f;
    }
    const float* Wp = W1 + ((size_t)l * 129 + half * 64) * 128;

    float acc[8][4] = {};
    for (int k0 = 0; k0 < 64; k0 += 16) {
        __syncthreads();
        #pragma unroll
        for (int it = 0; it < 8; ++it) {
            int idx = tid + it * 256;
            int col = idx & 127, kk = idx >> 7;
            ws[col * 20 + kk] = to_tf32(Wp[(size_t)(k0 + kk) * 128 + col]);
        }
        __syncthreads();
        #pragma unroll
        for (int ks = 0; ks < 16; ks += 8) {
            unsigned a0 = to_tf32(xs[(mb + g) * 68 + k0 + ks + tg]);
            unsigned a1 = to_tf32(xs[(mb + g + 8) * 68 + k0 + ks + tg]);
            unsigned a2 = to_tf32(xs[(mb + g) * 68 + k0 + ks + tg + 4]);
            unsigned a3 = to_tf32(xs[(mb + g + 8) * 68 + k0 + ks + tg + 4]);
            #pragma unroll
            for (int nt = 0; nt < 8; ++nt) {
                unsigned b0 = ws[(nb + nt * 8 + g) * 20 + ks + tg];
                unsigned b1r = ws[(nb + nt * 8 + g) * 20 + ks + tg + 4];
                mma8(acc[nt], a0, a1, a2, a3, b0, b1r);
            }
        }
    }
    int row0 = n0 + mb + g, row1 = row0 + 8;
    #pragma unroll
    for (int nt = 0; nt < 8; ++nt) {
        int c0 = nb + nt * 8 + 2 * tg;
        float bb0 = (half == 0) ? b1[l * 128 + c0] : 0.0f;
        float bb1 = (half == 0) ? b1[l * 128 + c0 + 1] : 0.0f;
        if (row0 < NN) {
            g_AB[(size_t)row0 * 256 + half * 128 + c0]     = acc[nt][0] + bb0;
            g_AB[(size_t)row0 * 256 + half * 128 + c0 + 1] = acc[nt][1] + bb1;
        }
        if (row1 < NN) {
            g_AB[(size_t)row1 * 256 + half * 128 + c0]     = acc[nt][2] + bb0;
            g_AB[(size_t)row1 * 256 + half * 128 + c0 + 1] = acc[nt][3] + bb1;
        }
    }
}

// ---------------- k2: persistent edge MLP, bf16 mma, W2 resident ----------------
// smem (bytes): w2b bf16[128][136] @0 (34816) | union h1b bf16[64][136] / mf f32[64][132]
// @34816 (33792) | srcs@68608 | dsts@68864 | es@69120 | w1e@69376 | b2s@69888 ; tot 70400
#define K2_GRID 444
#define K2_SMEM 70400
__global__ void __launch_bounds__(256, 3) k2_edge(int l, const int* __restrict__ ei,
                                                  const float* __restrict__ eattr,
                                                  const float* __restrict__ W1,
                                                  const float* __restrict__ W2,
                                                  const float* __restrict__ b2) {
    extern __shared__ char sm8[];
    __nv_bfloat16* w2b = (__nv_bfloat16*)sm8;
    __nv_bfloat16* h1b = (__nv_bfloat16*)(sm8 + 34816);
    float* mf = (float*)(sm8 + 34816);
    int* srcs = (int*)(sm8 + 68608);
    int* dsts = (int*)(sm8 + 68864);
    float* es = (float*)(sm8 + 69120);
    float* w1e = (float*)(sm8 + 69376);
    float* b2s = (float*)(sm8 + 69888);

    int tid = threadIdx.x, warp = tid >> 5, lane = tid & 31;
    int g = lane >> 2, tg = lane & 3;
    int mb = (warp & 3) * 16, nb = (warp >> 2) * 64;

    // stage W2 bf16 [col][k] pitch 136 (once)
    #pragma unroll
    for (int it = 0; it < 64; ++it) {
        int idx = tid + it * 256;              // 16384
        int col = idx & 127, kk = idx >> 7;
        w2b[col * 136 + kk] = __float2bfloat16(W2[((size_t)l * 128 + kk) * 128 + col]);
    }
    if (tid < 128) w1e[tid] = W1[((size_t)l * 129 + 128) * 128 + tid];
    else b2s[tid - 128] = b2[l * 128 + (tid - 128)];

    const float4* AB4 = (const float4*)g_AB;
    const float4* w1e4 = (const float4*)w1e;

    for (int t = blockIdx.x; t < NE / 64; t += K2_GRID) {
        int e0 = t * 64;
        __syncthreads();                       // prev reduce done / W2 staged
        if (tid < 64) {
            int e = g_perm[e0 + tid];
            srcs[tid] = ei[e];
            dsts[tid] = ei[NE + e];
            es[tid] = eattr[e];
        }
        __syncthreads();

        // phase A: h1 = softplus(A[dst] + B[src] + e*w1e) -> bf16
        #pragma unroll
        for (int it = 0; it < 8; ++it) {
            int idx = tid + it * 256;          // 2048
            int e = idx >> 5, q = idx & 31;
            float4 a = AB4[(size_t)dsts[e] * 64 + q];
            float4 b = AB4[(size_t)srcs[e] * 64 + 32 + q];
            float ev = es[e];
            float4 w = w1e4[q];
            float v0 = softplusf(a.x + b.x + ev * w.x);
            float v1 = softplusf(a.y + b.y + ev * w.y);
            float v2 = softplusf(a.z + b.z + ev * w.z);
            float v3 = softplusf(a.w + b.w + ev * w.w);
            uint2 r;
            r.x = pack_bf16(v0, v1);
            r.y = pack_bf16(v2, v3);
            *(uint2*)(h1b + e * 136 + q * 4) = r;
        }
        __syncthreads();

        // phase B: D = h1 @ W2, bf16 m16n8k16
        float acc[8][4] = {};
        #pragma unroll
        for (int kc = 0; kc < 128; kc += 16) {
            unsigned a0 = *(const unsigned*)(h1b + (mb + g) * 136 + kc + 2 * tg);
            unsigned a1 = *(const unsigned*)(h1b + (mb + g + 8) * 136 + kc + 2 * tg);
            unsigned a2 = *(const unsigned*)(h1b + (mb + g) * 136 + kc + 2 * tg + 8);
            unsigned a3 = *(const unsigned*)(h1b + (mb + g + 8) * 136 + kc + 2 * tg + 8);
            #pragma unroll
            for (int nt = 0; nt < 8; ++nt) {
                int col = nb + nt * 8 + g;
                unsigned b0 = *(const unsigned*)(w2b + col * 136 + kc + 2 * tg);
                unsigned b1r = *(const unsigned*)(w2b + col * 136 + kc + 2 * tg + 8);
                mma16bf(acc[nt], a0, a1, a2, a3, b0, b1r);
            }
        }
        __syncthreads();                       // h1b reads done before mf writes

        #pragma unroll
        for (int nt = 0; nt < 8; ++nt) {
            int c0 = nb + nt * 8 + 2 * tg;
            mf[(mb + g) * 132 + c0]         = softplusf(acc[nt][0] + b2s[c0]);
            mf[(mb + g) * 132 + c0 + 1]     = softplusf(acc[nt][1] + b2s[c0 + 1]);
            mf[(mb + g + 8) * 132 + c0]     = softplusf(acc[nt][2] + b2s[c0]);
            mf[(mb + g + 8) * 132 + c0 + 1] = softplusf(acc[nt][3] + b2s[c0 + 1]);
        }
        __syncthreads();

        // segmented reduction over sorted dst runs
        int c = tid & 127;
        int r0 = (tid >> 7) * 32;
        float racc = 0.0f;
        int prev = dsts[r0];
        #pragma unroll 4
        for (int r = r0; r < r0 + 32; ++r) {
            int d = dsts[r];
            if (d != prev) {
                atomicAdd(&g_aggr[(size_t)prev * 128 + c], racc);
                racc = 0.0f;
                prev = d;
            }
            racc += mf[r * 132 + c];
        }
        atomicAdd(&g_aggr[(size_t)prev * 128 + c], racc);
    }
}

// ---------------- k3: node MLP (both GEMMs tf32 mma) + residual + BN stats ----------------
__global__ void __launch_bounds__(256) k3_node(int l, const float* __restrict__ W1,
                                               const float* __restrict__ b1,
                                               const float* __restrict__ W2,
                                               const float* __restrict__ b2) {
    __shared__ float hs[32 * 196];
    __shared__ unsigned ws[128 * 20];
    __shared__ float ssum[64], ssq[64];
    int tid = threadIdx.x, warp = tid >> 5, lane = tid & 31;
    int g = lane >> 2, tg = lane & 3;
    int mb = (warp & 1) * 16, nb = (warp >> 1) * 32;
    int n0 = blockIdx.x * 32;

    if (tid < 64) { ssum[tid] = 0.0f; ssq[tid] = 0.0f; }
    for (int it = 0; it < 24; ++it) {
        int idx = tid + it * 256;
        int i = idx / 192, c = idx - i * 192;
        int node = n0 + i;
        float v = 0.0f;
        if (node < NN) v = (c < 64) ? g_x[(size_t)node * DD + c]
                                    : g_aggr[(size_t)node * HH + (c - 64)];
        hs[i * 196 + c] = v;
    }

    // GEMM1: t = softplus([x|aggr] @ nW1 + b1), M=32, N=128, K=192
    float acc[4][4] = {};
    for (int k0 = 0; k0 < 192; k0 += 16) {
        __syncthreads();
        #pragma unroll
        for (int it = 0; it < 8; ++it) {
            int idx = tid + it * 256;
            int col = idx & 127, kk = idx >> 7;
            ws[col * 20 + kk] = to_tf32(W1[((size_t)l * 192 + k0 + kk) * 128 + col]);
        }
        __syncthreads();
        #pragma unroll
        for (int ks = 0; ks < 16; ks += 8) {
            unsigned a0 = to_tf32(hs[(mb + g) * 196 + k0 + ks + tg]);
            unsigned a1 = to_tf32(hs[(mb + g + 8) * 196 + k0 + ks + tg]);
            unsigned a2 = to_tf32(hs[(mb + g) * 196 + k0 + ks + tg + 4]);
            unsigned a3 = to_tf32(hs[(mb + g + 8) * 196 + k0 + ks + tg + 4]);
            #pragma unroll
            for (int nt = 0; nt < 4; ++nt) {
                unsigned b0 = ws[(nb + nt * 8 + g) * 20 + ks + tg];
                unsigned b1r = ws[(nb + nt * 8 + g) * 20 + ks + tg + 4];
                mma8(acc[nt], a0, a1, a2, a3, b0, b1r);
            }
        }
    }
    __syncthreads();
    #pragma unroll
    for (int nt = 0; nt < 4; ++nt) {
        int c0 = nb + nt * 8 + 2 * tg;
        hs[(mb + g) * 196 + 64 + c0]         = softplusf(acc[nt][0] + b1[l * 128 + c0]);
        hs[(mb + g) * 196 + 64 + c0 + 1]     = softplusf(acc[nt][1] + b1[l * 128 + c0 + 1]);
        hs[(mb + g + 8) * 196 + 64 + c0]     = softplusf(acc[nt][2] + b1[l * 128 + c0]);
        hs[(mb + g + 8) * 196 + 64 + c0 + 1] = softplusf(acc[nt][3] + b1[l * 128 + c0 + 1]);
    }

    // GEMM2: y = t @ nW2 + b2 + x, M=32, N=64, K=128 (tf32 mma)
    int mb2 = (warp & 1) * 16, nb2 = (warp >> 1) * 16;
    float acc2[2][4] = {};
    for (int k0 = 0; k0 < 128; k0 += 16) {
        __syncthreads();
        #pragma unroll
        for (int it = 0; it < 4; ++it) {
            int idx = tid + it * 256;          // 1024
            int col = idx & 63, kk = idx >> 6;
            ws[col * 20 + kk] = to_tf32(W2[((size_t)l * 128 + k0 + kk) * 64 + col]);
        }
        __syncthreads();
        #pragma unroll
        for (int ks = 0; ks < 16; ks += 8) {
            unsigned a0 = to_tf32(hs[(mb2 + g) * 196 + 64 + k0 + ks + tg]);
            unsigned a1 = to_tf32(hs[(mb2 + g + 8) * 196 + 64 + k0 + ks + tg]);
            unsigned a2 = to_tf32(hs[(mb2 + g) * 196 + 64 + k0 + ks + tg + 4]);
            unsigned a3 = to_tf32(hs[(mb2 + g + 8) * 196 + 64 + k0 + ks + tg + 4]);
            #pragma unroll
            for (int nt = 0; nt < 2; ++nt) {
                unsigned b0 = ws[(nb2 + nt * 8 + g) * 20 + ks + tg];
                unsigned b1r = ws[(nb2 + nt * 8 + g) * 20 + ks + tg + 4];
                mma8(acc2[nt], a0, a1, a2, a3, b0, b1r);
            }
        }
    }

    // epilogue: y = acc2 + b2 + residual; write g_x; BN stats via smem atomics
    #pragma unroll
    for (int nt = 0; nt < 2; ++nt) {
        int c0 = nb2 + nt * 8 + 2 * tg;
        float bb0 = b2[l * 64 + c0], bb1 = b2[l * 64 + c0 + 1];
        int row0 = mb2 + g, row1 = mb2 + g + 8;
        int node0 = n0 + row0, node1 = n0 + row1;
        if (node0 < NN) {
            float y0 = acc2[nt][0] + bb0 + hs[row0 * 196 + c0];
            float y1 = acc2[nt][1] + bb1 + hs[row0 * 196 + c0 + 1];
            g_x[(size_t)node0 * DD + c0] = y0;
            g_x[(size_t)node0 * DD + c0 + 1] = y1;
            atomicAdd(&ssum[c0], y0);     atomicAdd(&ssum[c0 + 1], y1);
            atomicAdd(&ssq[c0], y0 * y0); atomicAdd(&ssq[c0 + 1], y1 * y1);
        }
        if (node1 < NN) {
            float y2 = acc2[nt][2] + bb0 + hs[row1 * 196 + c0];
            float y3 = acc2[nt][3] + bb1 + hs[row1 * 196 + c0 + 1];
            g_x[(size_t)node1 * DD + c0] = y2;
            g_x[(size_t)node1 * DD + c0 + 1] = y3;
            atomicAdd(&ssum[c0], y2);     atomicAdd(&ssum[c0 + 1], y3);
            atomicAdd(&ssq[c0], y2 * y2); atomicAdd(&ssq[c0 + 1], y3 * y3);
        }
    }
    __syncthreads();
    if (tid < 64) {
        atomicAdd(&g_stats[tid], ssum[tid]);
        atomicAdd(&g_stats[64 + tid], ssq[tid]);
    }
}

// ---------------- k4: batchnorm normalize ----------------
__global__ void k4_bn(int l, const float* __restrict__ gamma, const float* __restrict__ beta) {
    int idx = blockIdx.x * blockDim.x + threadIdx.x;
    if (idx >= NN * DD) return;
    int c = idx & 63;
    const float invN = 1.0f / (float)NN;
    float mu = g_stats[c] * invN;
    float var = g_stats[64 + c] * invN - mu * mu;
    float inv = rsqrtf(var + 1e-5f);
    float v = g_x[idx];
    g_x[idx] = gamma[l * 64 + c] * (v - mu) * inv + beta[l * 64 + c];
}

// ---------------- k5: global mean pool ----------------
__global__ void k5_pool(const int* __restrict__ batch) {
    int idx = blockIdx.x * blockDim.x + threadIdx.x;
    if (idx >= NN * DD) return;
    int i = idx >> 6, c = idx & 63;
    int b = batch[i];
    atomicAdd(&g_pool[b * DD + c], g_x[idx]);
    if (c == 0) atomicAdd(&g_cnt[b], 1.0f);
}

// ---------------- k6: output MLP ----------------
__global__ void k6_out(const float* __restrict__ W1, const float* __restrict__ b1,
                       const float* __restrict__ W2, const float* __restrict__ b2,
                       float* __restrict__ out) {
    __shared__ float p[64];
    __shared__ float red[128];
    int g = blockIdx.x, c = threadIdx.x;
    if (c < 64) p[c] = g_pool[g * DD + c] / fmaxf(g_cnt[g], 1.0f);
    __syncthreads();
    float acc = b1[c];
    #pragma unroll
    for (int d = 0; d < 64; ++d) acc = fmaf(p[d], W1[d * 128 + c], acc);
    red[c] = softplusf(acc) * W2[c];
    __syncthreads();
    for (int s = 64; s > 0; s >>= 1) {
        if (c < s) red[c] += red[c + s];
        __syncthreads();
    }
    if (c == 0) out[g] = red[0] + b2[0];
}

// ---------------- launcher ----------------
extern "C" void kernel_launch(void* const* d_in, const int* in_sizes, int n_in,
                              void* d_out, int out_size) {
    const int*   atom_z = (const int*)  d_in[0];
    const int*   ei     = (const int*)  d_in[1];
    const float* eattr  = (const float*)d_in[2];
    const int*   batch  = (const int*)  d_in[3];
    const float* emb    = (const float*)d_in[4];
    const float* eW1    = (const float*)d_in[5];
    const float* eb1    = (const float*)d_in[6];
    const float* eW2    = (const float*)d_in[7];
    const float* eb2    = (const float*)d_in[8];
    const float* nW1    = (const float*)d_in[9];
    const float* nb1    = (const float*)d_in[10];
    const float* nW2    = (const float*)d_in[11];
    const float* nb2    = (const float*)d_in[12];
    const float* bng    = (const float*)d_in[13];
    const float* bnb    = (const float*)d_in[14];
    const float* oW1    = (const float*)d_in[15];
    const float* ob1    = (const float*)d_in[16];
    const float* oW2    = (const float*)d_in[17];
    const float* ob2    = (const float*)d_in[18];
    float* out = (float*)d_out;

    cudaFuncSetAttribute(k2_edge, cudaFuncAttributeMaxDynamicSharedMemorySize, K2_SMEM);

    k0_embed<<<(NN * DD + 255) / 256, 256>>>(atom_z, emb);

    kz_hist<<<(NN + 255) / 256, 256>>>();
    k_hist<<<(NE + 255) / 256, 256>>>(ei);
    int nsb = (NN + 1023) / 1024;
    k_scan_part<<<nsb, 1024>>>();
    k_scan_top<<<1, 64>>>();
    k_scan_add<<<nsb, 1024>>>();
    k_scatter<<<(NE + 255) / 256, 256>>>(ei);

    for (int l = 0; l < NL; ++l) {
        kzero_layer<<<(NN * HH + 255) / 256, 256>>>();
        k1_AB<<<dim3((NN + 63) / 64, 2), 256>>>(l, eW1, eb1);
        k2_edge<<<K2_GRID, 256, K2_SMEM>>>(l, ei, eattr, eW1, eW2, eb2);
        k3_node<<<(NN + 31) / 32, 256>>>(l, nW1, nb1, nW2, nb2);
        k4_bn<<<(NN * DD + 255) / 256, 256>>>(l, bng, bnb);
    }
    kzero_pool<<<(GG * DD + 255) / 256, 256>>>();
    k5_pool<<<(NN * DD + 255) / 256, 256>>>(batch);
    k6_out<<<GG, 128>>>(oW1, ob1, oW2, ob2, out);
}

// round 5
// speedup vs baseline: 2.6161x; 1.0789x over previous
#include <cuda_runtime.h>
#include <cuda_bf16.h>
#include <math.h>

#define NN 50000
#define NE 800000
#define DD 64
#define HH 128
#define GG 128
#define NL 3

// ---------------- device scratch ----------------
__device__ float g_x[NN * DD];             // pre-BN node features
__device__ float g_AB[(size_t)NN * 256];   // [A=x'@W1a+b1 | B=x'@W1b] (x' = BN-applied)
__device__ float g_aggr[(size_t)NN * HH];
__device__ float g_stats[2][128];          // [buf][ sum(64) | sumsq(64) ]
__device__ float g_pool[GG * DD];
__device__ float g_cnt[GG];
__device__ int   g_hist[NN];
__device__ int   g_bsum[64];
__device__ int   g_perm[NE];

__device__ __forceinline__ float softplusf(float x) {
    return fmaxf(x, 0.0f) + __logf(1.0f + __expf(-fabsf(x)));
}
__device__ __forceinline__ unsigned to_tf32(float x) {
    unsigned u;
    asm("cvt.rna.tf32.f32 %0, %1;" : "=r"(u) : "f"(x));
    return u;
}
__device__ __forceinline__ unsigned pack_bf16(float lo, float hi) {
    unsigned r;
    asm("cvt.rn.bf16x2.f32 %0, %1, %2;" : "=r"(r) : "f"(hi), "f"(lo));
    return r;
}
__device__ __forceinline__ void mma8(float* c, unsigned a0, unsigned a1,
                                     unsigned a2, unsigned a3,
                                     unsigned b0, unsigned b1) {
    asm volatile(
        "mma.sync.aligned.m16n8k8.row.col.f32.tf32.tf32.f32 "
        "{%0,%1,%2,%3}, {%4,%5,%6,%7}, {%8,%9}, {%0,%1,%2,%3};"
        : "+f"(c[0]), "+f"(c[1]), "+f"(c[2]), "+f"(c[3])
        : "r"(a0), "r"(a1), "r"(a2), "r"(a3), "r"(b0), "r"(b1));
}
__device__ __forceinline__ void mma16bf(float* c, unsigned a0, unsigned a1,
                                        unsigned a2, unsigned a3,
                                        unsigned b0, unsigned b1) {
    asm volatile(
        "mma.sync.aligned.m16n8k16.row.col.f32.bf16.bf16.f32 "
        "{%0,%1,%2,%3}, {%4,%5,%6,%7}, {%8,%9}, {%0,%1,%2,%3};"
        : "+f"(c[0]), "+f"(c[1]), "+f"(c[2]), "+f"(c[3])
        : "r"(a0), "r"(a1), "r"(a2), "r"(a3), "r"(b0), "r"(b1));
}
// BN affine for layer l reads (applies BN of layer l-1; identity for l==0)
__device__ __forceinline__ void bn_coeff(int l, int c, const float* gamma,
                                         const float* beta, float& S, float& T) {
    if (l == 0) { S = 1.0f; T = 0.0f; return; }
    const float* sb = g_stats[(l - 1) & 1];
    const float invN = 1.0f / (float)NN;
    float mu = sb[c] * invN;
    float var = sb[64 + c] * invN - mu * mu;
    float gi = gamma[(l - 1) * 64 + c] * rsqrtf(var + 1e-5f);
    S = gi;
    T = beta[(l - 1) * 64 + c] - mu * gi;
}

// ---------------- k0: embedding gather ----------------
__global__ void k0_embed(const int* __restrict__ az, const float* __restrict__ emb) {
    int idx = blockIdx.x * blockDim.x + threadIdx.x;
    if (idx >= NN * DD) return;
    int i = idx >> 6, c = idx & 63;
    g_x[idx] = emb[az[i] * DD + c];
}

// ---------------- counting sort of edges by dst ----------------
__global__ void kz_hist() {
    int i = blockIdx.x * blockDim.x + threadIdx.x;
    if (i < NN) g_hist[i] = 0;
}
__global__ void k_hist(const int* __restrict__ ei) {
    int e = blockIdx.x * blockDim.x + threadIdx.x;
    if (e < NE) atomicAdd(&g_hist[ei[NE + e]], 1);
}
__global__ void k_scan_part() {
    __shared__ int wsum[32];
    int tid = threadIdx.x, lane = tid & 31, wid = tid >> 5;
    int i = blockIdx.x * 1024 + tid;
    int v = (i < NN) ? g_hist[i] : 0;
    int x = v;
    #pragma unroll
    for (int off = 1; off < 32; off <<= 1) {
        int y = __shfl_up_sync(0xffffffffu, x, off);
        if (lane >= off) x += y;
    }
    if (lane == 31) wsum[wid] = x;
    __syncthreads();
    if (wid == 0) {
        int s = wsum[lane];
        #pragma unroll
        for (int off = 1; off < 32; off <<= 1) {
            int y = __shfl_up_sync(0xffffffffu, s, off);
            if (lane >= off) s += y;
        }
        wsum[lane] = s;
    }
    __syncthreads();
    int woff = (wid > 0) ? wsum[wid - 1] : 0;
    if (i < NN) g_hist[i] = x - v + woff;
    if (tid == 1023) g_bsum[blockIdx.x] = x + woff;
}
__global__ void k_scan_top() {
    __shared__ int s[64];
    int tid = threadIdx.x;
    int nb = (NN + 1023) / 1024;
    int v = (tid < nb) ? g_bsum[tid] : 0;
    s[tid] = v;
    __syncthreads();
    for (int off = 1; off < 64; off <<= 1) {
        int t = (tid >= off) ? s[tid - off] : 0;
        __syncthreads();
        s[tid] += t;
        __syncthreads();
    }
    if (tid < nb) g_bsum[tid] = s[tid] - v;
}
__global__ void k_scan_add() {
    int i = blockIdx.x * 1024 + threadIdx.x;
    if (i < NN) g_hist[i] += g_bsum[blockIdx.x];
}
__global__ void k_scatter(const int* __restrict__ ei) {
    int e = blockIdx.x * blockDim.x + threadIdx.x;
    if (e >= NE) return;
    int d = ei[NE + e];
    int pos = atomicAdd(&g_hist[d], 1);
    g_perm[pos] = e;
}

__global__ void kzero_pool() {
    int i = blockIdx.x * blockDim.x + threadIdx.x;
    if (i < GG * DD) g_pool[i] = 0.0f;
    if (i < GG) g_cnt[i] = 0.0f;
}

// ---------------- k1: AB = x' @ [W1a | W1b]; also zeroes aggr + stats ----------------
__global__ void __launch_bounds__(256) k1_AB(int l, const float* __restrict__ W1,
                                             const float* __restrict__ b1,
                                             const float* __restrict__ gamma,
                                             const float* __restrict__ beta) {
    __shared__ float xs[64 * 68];
    __shared__ unsigned ws[128 * 20];
    __shared__ float bnS[64], bnT[64];
    int tid = threadIdx.x, warp = tid >> 5, lane = tid & 31;
    int g = lane >> 2, tg = lane & 3;
    int n0 = blockIdx.x * 64;
    int half = blockIdx.y;
    int mb = (warp & 3) * 16, nb = (warp >> 2) * 64;

    if (tid < 64) bn_coeff(l, tid, gamma, beta, bnS[tid], bnT[tid]);
    if (blockIdx.x == 0 && half == 0 && tid < 128) g_stats[l & 1][tid] = 0.0f;

    // zero this block's slice of g_aggr (nodes n0..n0+63, cols half*64..+63)
    {
        float4 z = make_float4(0.f, 0.f, 0.f, 0.f);
        float4* Az = (float4*)g_aggr;
        #pragma unroll
        for (int it = 0; it < 4; ++it) {
            int idx = tid + it * 256;          // 1024
            int i = idx >> 4, qc = idx & 15;
            int node = n0 + i;
            if (node < NN) Az[(size_t)node * 32 + half * 16 + qc] = z;
        }
    }
    __syncthreads();   // bnS ready

    #pragma unroll
    for (int it = 0; it < 16; ++it) {
        int idx = tid + it * 256;
        int i = idx >> 6, c = idx & 63;
        int node = n0 + i;
        float v = (node < NN) ? g_x[(size_t)node * DD + c] : 0.0f;
        xs[i * 68 + c] = v * bnS[c] + bnT[c];
    }
    const float* Wp = W1 + ((size_t)l * 129 + half * 64) * 128;

    float acc[8][4] = {};
    for (int k0 = 0; k0 < 64; k0 += 16) {
        __syncthreads();
        #pragma unroll
        for (int it = 0; it < 8; ++it) {
            int idx = tid + it * 256;
            int col = idx & 127, kk = idx >> 7;
            ws[col * 20 + kk] = to_tf32(Wp[(size_t)(k0 + kk) * 128 + col]);
        }
        __syncthreads();
        #pragma unroll
        for (int ks = 0; ks < 16; ks += 8) {
            unsigned a0 = to_tf32(xs[(mb + g) * 68 + k0 + ks + tg]);
            unsigned a1 = to_tf32(xs[(mb + g + 8) * 68 + k0 + ks + tg]);
            unsigned a2 = to_tf32(xs[(mb + g) * 68 + k0 + ks + tg + 4]);
            unsigned a3 = to_tf32(xs[(mb + g + 8) * 68 + k0 + ks + tg + 4]);
            #pragma unroll
            for (int nt = 0; nt < 8; ++nt) {
                unsigned b0 = ws[(nb + nt * 8 + g) * 20 + ks + tg];
                unsigned b1r = ws[(nb + nt * 8 + g) * 20 + ks + tg + 4];
                mma8(acc[nt], a0, a1, a2, a3, b0, b1r);
            }
        }
    }
    int row0 = n0 + mb + g, row1 = row0 + 8;
    #pragma unroll
    for (int nt = 0; nt < 8; ++nt) {
        int c0 = nb + nt * 8 + 2 * tg;
        float bb0 = (half == 0) ? b1[l * 128 + c0] : 0.0f;
        float bb1 = (half == 0) ? b1[l * 128 + c0 + 1] : 0.0f;
        if (row0 < NN) {
            g_AB[(size_t)row0 * 256 + half * 128 + c0]     = acc[nt][0] + bb0;
            g_AB[(size_t)row0 * 256 + half * 128 + c0 + 1] = acc[nt][1] + bb1;
        }
        if (row1 < NN) {
            g_AB[(size_t)row1 * 256 + half * 128 + c0]     = acc[nt][2] + bb0;
            g_AB[(size_t)row1 * 256 + half * 128 + c0 + 1] = acc[nt][3] + bb1;
        }
    }
}

// ---------------- k2: persistent edge MLP, bf16 mma, W2 resident ----------------
#define K2_GRID 444
#define K2_SMEM 70400
__global__ void __launch_bounds__(256, 3) k2_edge(int l, const int* __restrict__ ei,
                                                  const float* __restrict__ eattr,
                                                  const float* __restrict__ W1,
                                                  const float* __restrict__ W2,
                                                  const float* __restrict__ b2) {
    extern __shared__ char sm8[];
    __nv_bfloat16* w2b = (__nv_bfloat16*)sm8;
    __nv_bfloat16* h1b = (__nv_bfloat16*)(sm8 + 34816);
    float* mf = (float*)(sm8 + 34816);
    int* srcs = (int*)(sm8 + 68608);
    int* dsts = (int*)(sm8 + 68864);
    float* es = (float*)(sm8 + 69120);
    float* w1e = (float*)(sm8 + 69376);
    float* b2s = (float*)(sm8 + 69888);

    int tid = threadIdx.x, warp = tid >> 5, lane = tid & 31;
    int g = lane >> 2, tg = lane & 3;
    int mb = (warp & 3) * 16, nb = (warp >> 2) * 64;

    #pragma unroll
    for (int it = 0; it < 64; ++it) {
        int idx = tid + it * 256;
        int col = idx & 127, kk = idx >> 7;
        w2b[col * 136 + kk] = __float2bfloat16(W2[((size_t)l * 128 + kk) * 128 + col]);
    }
    if (tid < 128) w1e[tid] = W1[((size_t)l * 129 + 128) * 128 + tid];
    else b2s[tid - 128] = b2[l * 128 + (tid - 128)];

    const float4* AB4 = (const float4*)g_AB;
    const float4* w1e4 = (const float4*)w1e;

    for (int t = blockIdx.x; t < NE / 64; t += K2_GRID) {
        int e0 = t * 64;
        __syncthreads();
        if (tid < 64) {
            int e = g_perm[e0 + tid];
            srcs[tid] = ei[e];
            dsts[tid] = ei[NE + e];
            es[tid] = eattr[e];
        }
        __syncthreads();

        // phase A: warp-owned 8-edge strip; A[dst] quad reused across the run
        {
            int q = lane;
            int ebase = warp * 8;
            float4 aq = make_float4(0.f, 0.f, 0.f, 0.f);
            int prevd = -1;
            float4 w = w1e4[q];
            #pragma unroll
            for (int i = 0; i < 8; ++i) {
                int e = ebase + i;
                int d = dsts[e];
                if (d != prevd) { aq = AB4[(size_t)d * 64 + q]; prevd = d; }
                float4 b = AB4[(size_t)srcs[e] * 64 + 32 + q];
                float ev = es[e];
                float v0 = softplusf(aq.x + b.x + ev * w.x);
                float v1 = softplusf(aq.y + b.y + ev * w.y);
                float v2 = softplusf(aq.z + b.z + ev * w.z);
                float v3 = softplusf(aq.w + b.w + ev * w.w);
                uint2 r;
                r.x = pack_bf16(v0, v1);
                r.y = pack_bf16(v2, v3);
                *(uint2*)(h1b + e * 136 + q * 4) = r;
            }
        }
        __syncthreads();

        // phase B: D = h1 @ W2, bf16 m16n8k16
        float acc[8][4] = {};
        #pragma unroll
        for (int kc = 0; kc < 128; kc += 16) {
            unsigned a0 = *(const unsigned*)(h1b + (mb + g) * 136 + kc + 2 * tg);
            unsigned a1 = *(const unsigned*)(h1b + (mb + g + 8) * 136 + kc + 2 * tg);
            unsigned a2 = *(const unsigned*)(h1b + (mb + g) * 136 + kc + 2 * tg + 8);
            unsigned a3 = *(const unsigned*)(h1b + (mb + g + 8) * 136 + kc + 2 * tg + 8);
            #pragma unroll
            for (int nt = 0; nt < 8; ++nt) {
                int col = nb + nt * 8 + g;
                unsigned b0 = *(const unsigned*)(w2b + col * 136 + kc + 2 * tg);
                unsigned b1r = *(const unsigned*)(w2b + col * 136 + kc + 2 * tg + 8);
                mma16bf(acc[nt], a0, a1, a2, a3, b0, b1r);
            }
        }
        __syncthreads();

        #pragma unroll
        for (int nt = 0; nt < 8; ++nt) {
            int c0 = nb + nt * 8 + 2 * tg;
            mf[(mb + g) * 132 + c0]         = softplusf(acc[nt][0] + b2s[c0]);
            mf[(mb + g) * 132 + c0 + 1]     = softplusf(acc[nt][1] + b2s[c0 + 1]);
            mf[(mb + g + 8) * 132 + c0]     = softplusf(acc[nt][2] + b2s[c0]);
            mf[(mb + g + 8) * 132 + c0 + 1] = softplusf(acc[nt][3] + b2s[c0 + 1]);
        }
        __syncthreads();

        int c = tid & 127;
        int r0 = (tid >> 7) * 32;
        float racc = 0.0f;
        int prev = dsts[r0];
        #pragma unroll 4
        for (int r = r0; r < r0 + 32; ++r) {
            int d = dsts[r];
            if (d != prev) {
                atomicAdd(&g_aggr[(size_t)prev * 128 + c], racc);
                racc = 0.0f;
                prev = d;
            }
            racc += mf[r * 132 + c];
        }
        atomicAdd(&g_aggr[(size_t)prev * 128 + c], racc);
    }
}

// ---------------- k3: node MLP (M=64, tf32 mma) + residual + BN stats ----------------
// dyn smem floats: hs[64*196]@0 | ws u32[128*20]@50176B | ssum@60416 | ssq@60672
//                  bnS@60928 | bnT@61184 ; total 61440 B
#define K3_SMEM 61440
__global__ void __launch_bounds__(256, 3) k3_node(int l, const float* __restrict__ W1,
                                                  const float* __restrict__ b1,
                                                  const float* __restrict__ W2,
                                                  const float* __restrict__ b2,
                                                  const float* __restrict__ gamma,
                                                  const float* __restrict__ beta) {
    extern __shared__ char sm8[];
    float* hs = (float*)sm8;
    unsigned* ws = (unsigned*)(sm8 + 50176);
    float* ssum = (float*)(sm8 + 60416);
    float* ssq = (float*)(sm8 + 60672);
    float* bnS = (float*)(sm8 + 60928);
    float* bnT = (float*)(sm8 + 61184);

    int tid = threadIdx.x, warp = tid >> 5, lane = tid & 31;
    int g = lane >> 2, tg = lane & 3;
    int mb = (warp & 3) * 16, nb = (warp >> 2) * 64;
    int n0 = blockIdx.x * 64;

    if (tid < 64) {
        ssum[tid] = 0.0f; ssq[tid] = 0.0f;
        bn_coeff(l, tid, gamma, beta, bnS[tid], bnT[tid]);
    }
    __syncthreads();

    for (int it = 0; it < 48; ++it) {
        int idx = tid + it * 256;              // 12288
        int i = idx / 192, c = idx - i * 192;
        int node = n0 + i;
        float v = 0.0f;
        if (node < NN) {
            if (c < 64) v = g_x[(size_t)node * DD + c] * bnS[c] + bnT[c];
            else v = g_aggr[(size_t)node * HH + (c - 64)];
        }
        hs[i * 196 + c] = v;
    }

    // GEMM1: t = softplus([x'|aggr] @ nW1 + b1), M=64, N=128, K=192
    float acc[8][4] = {};
    for (int k0 = 0; k0 < 192; k0 += 16) {
        __syncthreads();
        #pragma unroll
        for (int it = 0; it < 8; ++it) {
            int idx = tid + it * 256;
            int col = idx & 127, kk = idx >> 7;
            ws[col * 20 + kk] = to_tf32(W1[((size_t)l * 192 + k0 + kk) * 128 + col]);
        }
        __syncthreads();
        #pragma unroll
        for (int ks = 0; ks < 16; ks += 8) {
            unsigned a0 = to_tf32(hs[(mb + g) * 196 + k0 + ks + tg]);
            unsigned a1 = to_tf32(hs[(mb + g + 8) * 196 + k0 + ks + tg]);
            unsigned a2 = to_tf32(hs[(mb + g) * 196 + k0 + ks + tg + 4]);
            unsigned a3 = to_tf32(hs[(mb + g + 8) * 196 + k0 + ks + tg + 4]);
            #pragma unroll
            for (int nt = 0; nt < 8; ++nt) {
                unsigned b0 = ws[(nb + nt * 8 + g) * 20 + ks + tg];
                unsigned b1r = ws[(nb + nt * 8 + g) * 20 + ks + tg + 4];
                mma8(acc[nt], a0, a1, a2, a3, b0, b1r);
            }
        }
    }
    __syncthreads();
    #pragma unroll
    for (int nt = 0; nt < 8; ++nt) {
        int c0 = nb + nt * 8 + 2 * tg;
        hs[(mb + g) * 196 + 64 + c0]         = softplusf(acc[nt][0] + b1[l * 128 + c0]);
        hs[(mb + g) * 196 + 64 + c0 + 1]     = softplusf(acc[nt][1] + b1[l * 128 + c0 + 1]);
        hs[(mb + g + 8) * 196 + 64 + c0]     = softplusf(acc[nt][2] + b1[l * 128 + c0]);
        hs[(mb + g + 8) * 196 + 64 + c0 + 1] = softplusf(acc[nt][3] + b1[l * 128 + c0 + 1]);
    }

    // GEMM2: y = t @ nW2 + b2 + x', M=64, N=64, K=128
    int nb2 = (warp >> 2) * 32;
    float acc2[4][4] = {};
    for (int k0 = 0; k0 < 128; k0 += 16) {
        __syncthreads();
        #pragma unroll
        for (int it = 0; it < 4; ++it) {
            int idx = tid + it * 256;          // 1024
            int col = idx & 63, kk = idx >> 6;
            ws[col * 20 + kk] = to_tf32(W2[((size_t)l * 128 + k0 + kk) * 64 + col]);
        }
        __syncthreads();
        #pragma unroll
        for (int ks = 0; ks < 16; ks += 8) {
            unsigned a0 = to_tf32(hs[(mb + g) * 196 + 64 + k0 + ks + tg]);
            unsigned a1 = to_tf32(hs[(mb + g + 8) * 196 + 64 + k0 + ks + tg]);
            unsigned a2 = to_tf32(hs[(mb + g) * 196 + 64 + k0 + ks + tg + 4]);
            unsigned a3 = to_tf32(hs[(mb + g + 8) * 196 + 64 + k0 + ks + tg + 4]);
            #pragma unroll
            for (int nt = 0; nt < 4; ++nt) {
                unsigned b0 = ws[(nb2 + nt * 8 + g) * 20 + ks + tg];
                unsigned b1r = ws[(nb2 + nt * 8 + g) * 20 + ks + tg + 4];
                mma8(acc2[nt], a0, a1, a2, a3, b0, b1r);
            }
        }
    }

    // epilogue: y = acc2 + b2 + residual(x'); write g_x (pre-BN); stats
    #pragma unroll
    for (int nt = 0; nt < 4; ++nt) {
        int c0 = nb2 + nt * 8 + 2 * tg;
        float bb0 = b2[l * 64 + c0], bb1 = b2[l * 64 + c0 + 1];
        int row0 = mb + g, row1 = mb + g + 8;
        int node0 = n0 + row0, node1 = n0 + row1;
        if (node0 < NN) {
            float y0 = acc2[nt][0] + bb0 + hs[row0 * 196 + c0];
            float y1 = acc2[nt][1] + bb1 + hs[row0 * 196 + c0 + 1];
            g_x[(size_t)node0 * DD + c0] = y0;
            g_x[(size_t)node0 * DD + c0 + 1] = y1;
            atomicAdd(&ssum[c0], y0);     atomicAdd(&ssum[c0 + 1], y1);
            atomicAdd(&ssq[c0], y0 * y0); atomicAdd(&ssq[c0 + 1], y1 * y1);
        }
        if (node1 < NN) {
            float y2 = acc2[nt][2] + bb0 + hs[row1 * 196 + c0];
            float y3 = acc2[nt][3] + bb1 + hs[row1 * 196 + c0 + 1];
            g_x[(size_t)node1 * DD + c0] = y2;
            g_x[(size_t)node1 * DD + c0 + 1] = y3;
            atomicAdd(&ssum[c0], y2);     atomicAdd(&ssum[c0 + 1], y3);
            atomicAdd(&ssq[c0], y2 * y2); atomicAdd(&ssq[c0 + 1], y3 * y3);
        }
    }
    __syncthreads();
    if (tid < 64) {
        atomicAdd(&g_stats[l & 1][tid], ssum[tid]);
        atomicAdd(&g_stats[l & 1][64 + tid], ssq[tid]);
    }
}

// ---------------- k5: global mean pool (applies final BN) ----------------
__global__ void k5_pool(const int* __restrict__ batch,
                        const float* __restrict__ gamma, const float* __restrict__ beta) {
    int idx = blockIdx.x * blockDim.x + threadIdx.x;
    if (idx >= NN * DD) return;
    int i = idx >> 6, c = idx & 63;
    const float* sb = g_stats[(NL - 1) & 1];
    const float invN = 1.0f / (float)NN;
    float mu = sb[c] * invN;
    float var = sb[64 + c] * invN - mu * mu;
    float gi = gamma[(NL - 1) * 64 + c] * rsqrtf(var + 1e-5f);
    float v = g_x[idx] * gi + (beta[(NL - 1) * 64 + c] - mu * gi);
    int b = batch[i];
    atomicAdd(&g_pool[b * DD + c], v);
    if (c == 0) atomicAdd(&g_cnt[b], 1.0f);
}

// ---------------- k6: output MLP ----------------
__global__ void k6_out(const float* __restrict__ W1, const float* __restrict__ b1,
                       const float* __restrict__ W2, const float* __restrict__ b2,
                       float* __restrict__ out) {
    __shared__ float p[64];
    __shared__ float red[128];
    int g = blockIdx.x, c = threadIdx.x;
    if (c < 64) p[c] = g_pool[g * DD + c] / fmaxf(g_cnt[g], 1.0f);
    __syncthreads();
    float acc = b1[c];
    #pragma unroll
    for (int d = 0; d < 64; ++d) acc = fmaf(p[d], W1[d * 128 + c], acc);
    red[c] = softplusf(acc) * W2[c];
    __syncthreads();
    for (int s = 64; s > 0; s >>= 1) {
        if (c < s) red[c] += red[c + s];
        __syncthreads();
    }
    if (c == 0) out[g] = red[0] + b2[0];
}

// ---------------- launcher ----------------
extern "C" void kernel_launch(void* const* d_in, const int* in_sizes, int n_in,
                              void* d_out, int out_size) {
    const int*   atom_z = (const int*)  d_in[0];
    const int*   ei     = (const int*)  d_in[1];
    const float* eattr  = (const float*)d_in[2];
    const int*   batch  = (const int*)  d_in[3];
    const float* emb    = (const float*)d_in[4];
    const float* eW1    = (const float*)d_in[5];
    const float* eb1    = (const float*)d_in[6];
    const float* eW2    = (const float*)d_in[7];
    const float* eb2    = (const float*)d_in[8];
    const float* nW1    = (const float*)d_in[9];
    const float* nb1    = (const float*)d_in[10];
    const float* nW2    = (const float*)d_in[11];
    const float* nb2    = (const float*)d_in[12];
    const float* bng    = (const float*)d_in[13];
    const float* bnb    = (const float*)d_in[14];
    const float* oW1    = (const float*)d_in[15];
    const float* ob1    = (const float*)d_in[16];
    const float* oW2    = (const float*)d_in[17];
    const float* ob2    = (const float*)d_in[18];
    float* out = (float*)d_out;

    cudaFuncSetAttribute(k2_edge, cudaFuncAttributeMaxDynamicSharedMemorySize, K2_SMEM);
    cudaFuncSetAttribute(k3_node, cudaFuncAttributeMaxDynamicSharedMemorySize, K3_SMEM);

    k0_embed<<<(NN * DD + 255) / 256, 256>>>(atom_z, emb);

    kz_hist<<<(NN + 255) / 256, 256>>>();
    k_hist<<<(NE + 255) / 256, 256>>>(ei);
    int nsb = (NN + 1023) / 1024;
    k_scan_part<<<nsb, 1024>>>();
    k_scan_top<<<1, 64>>>();
    k_scan_add<<<nsb, 1024>>>();
    k_scatter<<<(NE + 255) / 256, 256>>>(ei);

    for (int l = 0; l < NL; ++l) {
        k1_AB<<<dim3((NN + 63) / 64, 2), 256>>>(l, eW1, eb1, bng, bnb);
        k2_edge<<<K2_GRID, 256, K2_SMEM>>>(l, ei, eattr, eW1, eW2, eb2);
        k3_node<<<(NN + 63) / 64, 256, K3_SMEM>>>(l, nW1, nb1, nW2, nb2, bng, bnb);
    }
    kzero_pool<<<(GG * DD + 255) / 256, 256>>>();
    k5_pool<<<(NN * DD + 255) / 256, 256>>>(batch, bng, bnb);
    k6_out<<<GG, 128>>>(oW1, ob1, oW2, ob2, out);
}

// round 6
// speedup vs baseline: 2.7413x; 1.0478x over previous
#include <cuda_runtime.h>
#include <cuda_bf16.h>
#include <math.h>

#define NN 50000
#define NE 800000
#define DD 64
#define HH 128
#define GG 128
#define NL 3
#define NT (NE / 64)

// ---------------- device scratch ----------------
__device__ float g_x[NN * DD];             // pre-BN node features
__device__ float g_AB[(size_t)NN * 256];   // [A=x'@W1a+b1 | B=x'@W1b]
__device__ float g_aggr[(size_t)NN * HH];
__device__ float g_stats[2][128];
__device__ float g_pool[GG * DD];
__device__ float g_cnt[GG];
__device__ int   g_hist[NN];
__device__ int   g_bsum[64];
__device__ int   g_perm[NE];

// exact softplus (output MLP only)
__device__ __forceinline__ float softplusf(float x) {
    return fmaxf(x, 0.0f) + __logf(1.0f + __expf(-fabsf(x)));
}
// fast softplus: 1 MUFU + poly for ln(1+u), u=e^-|x| in [0,1]; |err| <~ 3e-4 abs
__device__ __forceinline__ float spf(float x) {
    float u = __expf(-fabsf(x));
    float p = fmaf(0.0834f, u, -0.2474f);
    p = fmaf(p, u, 0.4427f);
    float l = 0.6931472f * u * fmaf(1.0f - u, p, 1.0f);
    return fmaxf(x, 0.0f) + l;
}
__device__ __forceinline__ unsigned to_tf32(float x) {
    unsigned u;
    asm("cvt.rna.tf32.f32 %0, %1;" : "=r"(u) : "f"(x));
    return u;
}
__device__ __forceinline__ unsigned pack_bf16(float lo, float hi) {
    unsigned r;
    asm("cvt.rn.bf16x2.f32 %0, %1, %2;" : "=r"(r) : "f"(hi), "f"(lo));
    return r;
}
__device__ __forceinline__ void mma8(float* c, unsigned a0, unsigned a1,
                                     unsigned a2, unsigned a3,
                                     unsigned b0, unsigned b1) {
    asm volatile(
        "mma.sync.aligned.m16n8k8.row.col.f32.tf32.tf32.f32 "
        "{%0,%1,%2,%3}, {%4,%5,%6,%7}, {%8,%9}, {%0,%1,%2,%3};"
        : "+f"(c[0]), "+f"(c[1]), "+f"(c[2]), "+f"(c[3])
        : "r"(a0), "r"(a1), "r"(a2), "r"(a3), "r"(b0), "r"(b1));
}
__device__ __forceinline__ void mma16bf(float* c, unsigned a0, unsigned a1,
                                        unsigned a2, unsigned a3,
                                        unsigned b0, unsigned b1) {
    asm volatile(
        "mma.sync.aligned.m16n8k16.row.col.f32.bf16.bf16.f32 "
        "{%0,%1,%2,%3}, {%4,%5,%6,%7}, {%8,%9}, {%0,%1,%2,%3};"
        : "+f"(c[0]), "+f"(c[1]), "+f"(c[2]), "+f"(c[3])
        : "r"(a0), "r"(a1), "r"(a2), "r"(a3), "r"(b0), "r"(b1));
}
__device__ __forceinline__ void bn_coeff(int l, int c, const float* gamma,
                                         const float* beta, float& S, float& T) {
    if (l == 0) { S = 1.0f; T = 0.0f; return; }
    const float* sb = g_stats[(l - 1) & 1];
    const float invN = 1.0f / (float)NN;
    float mu = sb[c] * invN;
    float var = sb[64 + c] * invN - mu * mu;
    float gi = gamma[(l - 1) * 64 + c] * rsqrtf(var + 1e-5f);
    S = gi;
    T = beta[(l - 1) * 64 + c] - mu * gi;
}

// ---------------- k0: embedding gather (+ zero g_hist) ----------------
__global__ void k0_embed(const int* __restrict__ az, const float* __restrict__ emb) {
    int idx = blockIdx.x * blockDim.x + threadIdx.x;
    if (idx < NN) g_hist[idx] = 0;
    if (idx >= NN * DD) return;
    int i = idx >> 6, c = idx & 63;
    g_x[idx] = emb[az[i] * DD + c];
}

// ---------------- counting sort of edges by dst ----------------
__global__ void k_hist(const int* __restrict__ ei) {
    int e = blockIdx.x * blockDim.x + threadIdx.x;
    if (e < NE) atomicAdd(&g_hist[ei[NE + e]], 1);
}
__global__ void k_scan_part() {
    __shared__ int wsum[32];
    int tid = threadIdx.x, lane = tid & 31, wid = tid >> 5;
    int i = blockIdx.x * 1024 + tid;
    int v = (i < NN) ? g_hist[i] : 0;
    int x = v;
    #pragma unroll
    for (int off = 1; off < 32; off <<= 1) {
        int y = __shfl_up_sync(0xffffffffu, x, off);
        if (lane >= off) x += y;
    }
    if (lane == 31) wsum[wid] = x;
    __syncthreads();
    if (wid == 0) {
        int s = wsum[lane];
        #pragma unroll
        for (int off = 1; off < 32; off <<= 1) {
            int y = __shfl_up_sync(0xffffffffu, s, off);
            if (lane >= off) s += y;
        }
        wsum[lane] = s;
    }
    __syncthreads();
    int woff = (wid > 0) ? wsum[wid - 1] : 0;
    if (i < NN) g_hist[i] = x - v + woff;   // block-local exclusive
    if (tid == 1023) g_bsum[blockIdx.x] = x + woff;
}
__global__ void k_scan_top() {
    __shared__ int s[64];
    int tid = threadIdx.x;
    int nb = (NN + 1023) / 1024;
    int v = (tid < nb) ? g_bsum[tid] : 0;
    s[tid] = v;
    __syncthreads();
    for (int off = 1; off < 64; off <<= 1) {
        int t = (tid >= off) ? s[tid - off] : 0;
        __syncthreads();
        s[tid] += t;
        __syncthreads();
    }
    if (tid < nb) g_bsum[tid] = s[tid] - v;
}
__global__ void k_scatter(const int* __restrict__ ei) {
    int e = blockIdx.x * blockDim.x + threadIdx.x;
    if (e >= NE) return;
    int d = ei[NE + e];
    int pos = atomicAdd(&g_hist[d], 1) + g_bsum[d >> 10];
    g_perm[pos] = e;
}

__global__ void kzero_pool() {
    int i = blockIdx.x * blockDim.x + threadIdx.x;
    if (i < GG * DD) g_pool[i] = 0.0f;
    if (i < GG) g_cnt[i] = 0.0f;
}

// ---------------- k1: AB = x' @ [W1a | W1b]; zeroes aggr + stats ----------------
__global__ void __launch_bounds__(256) k1_AB(int l, const float* __restrict__ W1,
                                             const float* __restrict__ b1,
                                             const float* __restrict__ gamma,
                                             const float* __restrict__ beta) {
    __shared__ float xs[64 * 68];
    __shared__ unsigned ws[128 * 20];
    __shared__ float bnS[64], bnT[64];
    int tid = threadIdx.x, warp = tid >> 5, lane = tid & 31;
    int g = lane >> 2, tg = lane & 3;
    int n0 = blockIdx.x * 64;
    int half = blockIdx.y;
    int mb = (warp & 3) * 16, nb = (warp >> 2) * 64;

    if (tid < 64) bn_coeff(l, tid, gamma, beta, bnS[tid], bnT[tid]);
    if (blockIdx.x == 0 && half == 0 && tid < 128) g_stats[l & 1][tid] = 0.0f;

    {
        float4 z = make_float4(0.f, 0.f, 0.f, 0.f);
        float4* Az = (float4*)g_aggr;
        #pragma unroll
        for (int it = 0; it < 4; ++it) {
            int idx = tid + it * 256;
            int i = idx >> 4, qc = idx & 15;
            int node = n0 + i;
            if (node < NN) Az[(size_t)node * 32 + half * 16 + qc] = z;
        }
    }
    __syncthreads();

    #pragma unroll
    for (int it = 0; it < 16; ++it) {
        int idx = tid + it * 256;
        int i = idx >> 6, c = idx & 63;
        int node = n0 + i;
        float v = (node < NN) ? g_x[(size_t)node * DD + c] : 0.0f;
        xs[i * 68 + c] = v * bnS[c] + bnT[c];
    }
    const float* Wp = W1 + ((size_t)l * 129 + half * 64) * 128;

    float acc[8][4] = {};
    for (int k0 = 0; k0 < 64; k0 += 16) {
        __syncthreads();
        #pragma unroll
        for (int it = 0; it < 8; ++it) {
            int idx = tid + it * 256;
            int col = idx & 127, kk = idx >> 7;
            ws[col * 20 + kk] = to_tf32(Wp[(size_t)(k0 + kk) * 128 + col]);
        }
        __syncthreads();
        #pragma unroll
        for (int ks = 0; ks < 16; ks += 8) {
            unsigned a0 = to_tf32(xs[(mb + g) * 68 + k0 + ks + tg]);
            unsigned a1 = to_tf32(xs[(mb + g + 8) * 68 + k0 + ks + tg]);
            unsigned a2 = to_tf32(xs[(mb + g) * 68 + k0 + ks + tg + 4]);
            unsigned a3 = to_tf32(xs[(mb + g + 8) * 68 + k0 + ks + tg + 4]);
            #pragma unroll
            for (int nt = 0; nt < 8; ++nt) {
                unsigned b0 = ws[(nb + nt * 8 + g) * 20 + ks + tg];
                unsigned b1r = ws[(nb + nt * 8 + g) * 20 + ks + tg + 4];
                mma8(acc[nt], a0, a1, a2, a3, b0, b1r);
            }
        }
    }
    int row0 = n0 + mb + g, row1 = row0 + 8;
    #pragma unroll
    for (int nt = 0; nt < 8; ++nt) {
        int c0 = nb + nt * 8 + 2 * tg;
        float bb0 = (half == 0) ? b1[l * 128 + c0] : 0.0f;
        float bb1 = (half == 0) ? b1[l * 128 + c0 + 1] : 0.0f;
        if (row0 < NN) {
            g_AB[(size_t)row0 * 256 + half * 128 + c0]     = acc[nt][0] + bb0;
            g_AB[(size_t)row0 * 256 + half * 128 + c0 + 1] = acc[nt][1] + bb1;
        }
        if (row1 < NN) {
            g_AB[(size_t)row1 * 256 + half * 128 + c0]     = acc[nt][2] + bb0;
            g_AB[(size_t)row1 * 256 + half * 128 + c0 + 1] = acc[nt][3] + bb1;
        }
    }
}

// ---------------- k2: persistent, software-pipelined edge MLP ----------------
// smem: w2b bf16[128][136]@0 | h1 bf16[2][64*136]@34816 (m overlays in bf16)
//       srcs2[2][64]@69632 | es2[2][64]@70144 | dsts3[3][64]@70656
//       w1e[128]@71424 | b2s[128]@71936 ; total 72448
#define K2_GRID 444
#define K2_SMEM 72448
__global__ void __launch_bounds__(256, 3) k2_edge(int l, const int* __restrict__ ei,
                                                  const float* __restrict__ eattr,
                                                  const float* __restrict__ W1,
                                                  const float* __restrict__ W2,
                                                  const float* __restrict__ b2) {
    extern __shared__ char sm8[];
    __nv_bfloat16* w2b = (__nv_bfloat16*)sm8;
    __nv_bfloat16* h1base = (__nv_bfloat16*)(sm8 + 34816);
    int* srcs2 = (int*)(sm8 + 69632);
    float* es2 = (float*)(sm8 + 70144);
    int* dsts3 = (int*)(sm8 + 70656);
    float* w1e = (float*)(sm8 + 71424);
    float* b2s = (float*)(sm8 + 71936);

    int tid = threadIdx.x, warp = tid >> 5, lane = tid & 31;
    int g = lane >> 2, tg = lane & 3;
    int mb = (warp & 3) * 16, nb = (warp >> 2) * 64;

    // stage W2 bf16 [col][k] pitch 136 (once)
    #pragma unroll
    for (int it = 0; it < 64; ++it) {
        int idx = tid + it * 256;
        int col = idx & 127, kk = idx >> 7;
        w2b[col * 136 + kk] = __float2bfloat16(W2[((size_t)l * 128 + kk) * 128 + col]);
    }
    if (tid < 128) w1e[tid] = W1[((size_t)l * 129 + 128) * 128 + tid];
    else b2s[tid - 128] = b2[l * 128 + (tid - 128)];

    const float4* AB4 = (const float4*)g_AB;
    const float4* w1e4 = (const float4*)w1e;

    // helper lambdas (inlined)
    auto stage = [&](int tt, int s, int ds) {
        int e = g_perm[tt * 64 + tid];
        srcs2[s * 64 + tid] = ei[e];
        dsts3[ds * 64 + tid] = ei[NE + e];
        es2[s * 64 + tid] = eattr[e];
    };
    auto phaseA = [&](__nv_bfloat16* H, int s, int ds) {
        int q = lane;
        int eb = warp * 8;
        const int* S = srcs2 + s * 64;
        const float* E = es2 + s * 64;
        const int* D = dsts3 + ds * 64;
        float4 w = w1e4[q];
        float4 aq = make_float4(0.f, 0.f, 0.f, 0.f);
        int prevd = -1;
        #pragma unroll
        for (int j = 0; j < 8; ++j) {
            int e = eb + j;
            int d = D[e];
            if (d != prevd) { aq = AB4[(size_t)d * 64 + q]; prevd = d; }
            float4 b = AB4[(size_t)S[e] * 64 + 32 + q];
            float ev = E[e];
            uint2 r;
            r.x = pack_bf16(spf(aq.x + b.x + ev * w.x), spf(aq.y + b.y + ev * w.y));
            r.y = pack_bf16(spf(aq.z + b.z + ev * w.z), spf(aq.w + b.w + ev * w.w));
            *(uint2*)(H + e * 136 + q * 4) = r;
        }
    };

    int t0 = blockIdx.x;
    // prologue: idx(t0)->slot0/d0 ; phaseA(t0)->h1[0] ; idx(t0+G)->slot1/d1
    if (t0 < NT && tid < 64) stage(t0, 0, 0);
    __syncthreads();
    if (t0 < NT) phaseA(h1base, 0, 0);
    if (t0 + K2_GRID < NT && tid < 64) stage(t0 + K2_GRID, 1, 1);
    __syncthreads();

    int i = 0;
    for (int t = t0; t < NT; t += K2_GRID, ++i) {
        int p = i & 1, q2 = 1 - p;
        int d_cur = i % 3, d_nxt = (i + 1) % 3, d_stg = (i + 2) % 3;
        __nv_bfloat16* h1p = h1base + p * (64 * 136);
        __nv_bfloat16* h1q = h1base + q2 * (64 * 136);

        // 1. phase B on h1p (no sync needed before)
        float acc[8][4] = {};
        #pragma unroll
        for (int kc = 0; kc < 128; kc += 16) {
            unsigned a0 = *(const unsigned*)(h1p + (mb + g) * 136 + kc + 2 * tg);
            unsigned a1 = *(const unsigned*)(h1p + (mb + g + 8) * 136 + kc + 2 * tg);
            unsigned a2 = *(const unsigned*)(h1p + (mb + g) * 136 + kc + 2 * tg + 8);
            unsigned a3 = *(const unsigned*)(h1p + (mb + g + 8) * 136 + kc + 2 * tg + 8);
            #pragma unroll
            for (int nt = 0; nt < 8; ++nt) {
                int col = nb + nt * 8 + g;
                unsigned b0 = *(const unsigned*)(w2b + col * 136 + kc + 2 * tg);
                unsigned b1r = *(const unsigned*)(w2b + col * 136 + kc + 2 * tg + 8);
                mma16bf(acc[nt], a0, a1, a2, a3, b0, b1r);
            }
        }

        // 2. phase A for t+G into h1q (overlaps MMA tail; disjoint smem)
        int tn = t + K2_GRID;
        if (tn < NT) phaseA(h1q, q2, d_nxt);

        // 3. stage idx for t+2G into slot p / d_stg
        int ts = t + 2 * K2_GRID;
        if (ts < NT && tid < 64) stage(ts, p, d_stg);
        __syncthreads();

        // 4. epilogue: m = spf(D + b2) -> bf16 over h1p
        #pragma unroll
        for (int nt = 0; nt < 8; ++nt) {
            int c0 = nb + nt * 8 + 2 * tg;
            unsigned u0 = pack_bf16(spf(acc[nt][0] + b2s[c0]), spf(acc[nt][1] + b2s[c0 + 1]));
            unsigned u1 = pack_bf16(spf(acc[nt][2] + b2s[c0]), spf(acc[nt][3] + b2s[c0 + 1]));
            *(unsigned*)(h1p + (mb + g) * 136 + c0) = u0;
            *(unsigned*)(h1p + (mb + g + 8) * 136 + c0) = u1;
        }
        __syncthreads();

        // 5. segmented reduction over sorted dst runs (bf16 m)
        {
            const int* D = dsts3 + d_cur * 64;
            int c = tid & 127;
            int r0 = (tid >> 7) * 32;
            float racc = 0.0f;
            int prev = D[r0];
            #pragma unroll 4
            for (int r = r0; r < r0 + 32; ++r) {
                int d = D[r];
                if (d != prev) {
                    atomicAdd(&g_aggr[(size_t)prev * 128 + c], racc);
                    racc = 0.0f;
                    prev = d;
                }
                racc += __bfloat162float(h1p[r * 136 + c]);
            }
            atomicAdd(&g_aggr[(size_t)prev * 128 + c], racc);
        }
        __syncthreads();
    }
}

// ---------------- k3: node MLP (M=64, tf32 mma) + residual + BN stats ----------------
#define K3_SMEM 61440
__global__ void __launch_bounds__(256, 3) k3_node(int l, const float* __restrict__ W1,
                                                  const float* __restrict__ b1,
                                                  const float* __restrict__ W2,
                                                  const float* __restrict__ b2,
                                                  const float* __restrict__ gamma,
                                                  const float* __restrict__ beta) {
    extern __shared__ char sm8[];
    float* hs = (float*)sm8;
    unsigned* ws = (unsigned*)(sm8 + 50176);
    float* ssum = (float*)(sm8 + 60416);
    float* ssq = (float*)(sm8 + 60672);
    float* bnS = (float*)(sm8 + 60928);
    float* bnT = (float*)(sm8 + 61184);

    int tid = threadIdx.x, warp = tid >> 5, lane = tid & 31;
    int g = lane >> 2, tg = lane & 3;
    int mb = (warp & 3) * 16, nb = (warp >> 2) * 64;
    int n0 = blockIdx.x * 64;

    if (tid < 64) {
        ssum[tid] = 0.0f; ssq[tid] = 0.0f;
        bn_coeff(l, tid, gamma, beta, bnS[tid], bnT[tid]);
    }
    __syncthreads();

    for (int it = 0; it < 48; ++it) {
        int idx = tid + it * 256;
        int i = idx / 192, c = idx - i * 192;
        int node = n0 + i;
        float v = 0.0f;
        if (node < NN) {
            if (c < 64) v = g_x[(size_t)node * DD + c] * bnS[c] + bnT[c];
            else v = g_aggr[(size_t)node * HH + (c - 64)];
        }
        hs[i * 196 + c] = v;
    }

    float acc[8][4] = {};
    for (int k0 = 0; k0 < 192; k0 += 16) {
        __syncthreads();
        #pragma unroll
        for (int it = 0; it < 8; ++it) {
            int idx = tid + it * 256;
            int col = idx & 127, kk = idx >> 7;
            ws[col * 20 + kk] = to_tf32(W1[((size_t)l * 192 + k0 + kk) * 128 + col]);
        }
        __syncthreads();
        #pragma unroll
        for (int ks = 0; ks < 16; ks += 8) {
            unsigned a0 = to_tf32(hs[(mb + g) * 196 + k0 + ks + tg]);
            unsigned a1 = to_tf32(hs[(mb + g + 8) * 196 + k0 + ks + tg]);
            unsigned a2 = to_tf32(hs[(mb + g) * 196 + k0 + ks + tg + 4]);
            unsigned a3 = to_tf32(hs[(mb + g + 8) * 196 + k0 + ks + tg + 4]);
            #pragma unroll
            for (int nt = 0; nt < 8; ++nt) {
                unsigned b0 = ws[(nb + nt * 8 + g) * 20 + ks + tg];
                unsigned b1r = ws[(nb + nt * 8 + g) * 20 + ks + tg + 4];
                mma8(acc[nt], a0, a1, a2, a3, b0, b1r);
            }
        }
    }
    __syncthreads();
    #pragma unroll
    for (int nt = 0; nt < 8; ++nt) {
        int c0 = nb + nt * 8 + 2 * tg;
        hs[(mb + g) * 196 + 64 + c0]         = spf(acc[nt][0] + b1[l * 128 + c0]);
        hs[(mb + g) * 196 + 64 + c0 + 1]     = spf(acc[nt][1] + b1[l * 128 + c0 + 1]);
        hs[(mb + g + 8) * 196 + 64 + c0]     = spf(acc[nt][2] + b1[l * 128 + c0]);
        hs[(mb + g + 8) * 196 + 64 + c0 + 1] = spf(acc[nt][3] + b1[l * 128 + c0 + 1]);
    }

    int nb2 = (warp >> 2) * 32;
    float acc2[4][4] = {};
    for (int k0 = 0; k0 < 128; k0 += 16) {
        __syncthreads();
        #pragma unroll
        for (int it = 0; it < 4; ++it) {
            int idx = tid + it * 256;
            int col = idx & 63, kk = idx >> 6;
            ws[col * 20 + kk] = to_tf32(W2[((size_t)l * 128 + k0 + kk) * 64 + col]);
        }
        __syncthreads();
        #pragma unroll
        for (int ks = 0; ks < 16; ks += 8) {
            unsigned a0 = to_tf32(hs[(mb + g) * 196 + 64 + k0 + ks + tg]);
            unsigned a1 = to_tf32(hs[(mb + g + 8) * 196 + 64 + k0 + ks + tg]);
            unsigned a2 = to_tf32(hs[(mb + g) * 196 + 64 + k0 + ks + tg + 4]);
            unsigned a3 = to_tf32(hs[(mb + g + 8) * 196 + 64 + k0 + ks + tg + 4]);
            #pragma unroll
            for (int nt = 0; nt < 4; ++nt) {
                unsigned b0 = ws[(nb2 + nt * 8 + g) * 20 + ks + tg];
                unsigned b1r = ws[(nb2 + nt * 8 + g) * 20 + ks + tg + 4];
                mma8(acc2[nt], a0, a1, a2, a3, b0, b1r);
            }
        }
    }

    #pragma unroll
    for (int nt = 0; nt < 4; ++nt) {
        int c0 = nb2 + nt * 8 + 2 * tg;
        float bb0 = b2[l * 64 + c0], bb1 = b2[l * 64 + c0 + 1];
        int row0 = mb + g, row1 = mb + g + 8;
        int node0 = n0 + row0, node1 = n0 + row1;
        if (node0 < NN) {
            float y0 = acc2[nt][0] + bb0 + hs[row0 * 196 + c0];
            float y1 = acc2[nt][1] + bb1 + hs[row0 * 196 + c0 + 1];
            g_x[(size_t)node0 * DD + c0] = y0;
            g_x[(size_t)node0 * DD + c0 + 1] = y1;
            atomicAdd(&ssum[c0], y0);     atomicAdd(&ssum[c0 + 1], y1);
            atomicAdd(&ssq[c0], y0 * y0); atomicAdd(&ssq[c0 + 1], y1 * y1);
        }
        if (node1 < NN) {
            float y2 = acc2[nt][2] + bb0 + hs[row1 * 196 + c0];
            float y3 = acc2[nt][3] + bb1 + hs[row1 * 196 + c0 + 1];
            g_x[(size_t)node1 * DD + c0] = y2;
            g_x[(size_t)node1 * DD + c0 + 1] = y3;
            atomicAdd(&ssum[c0], y2);     atomicAdd(&ssum[c0 + 1], y3);
            atomicAdd(&ssq[c0], y2 * y2); atomicAdd(&ssq[c0 + 1], y3 * y3);
        }
    }
    __syncthreads();
    if (tid < 64) {
        atomicAdd(&g_stats[l & 1][tid], ssum[tid]);
        atomicAdd(&g_stats[l & 1][64 + tid], ssq[tid]);
    }
}

// ---------------- k5: global mean pool (applies final BN) ----------------
__global__ void k5_pool(const int* __restrict__ batch,
                        const float* __restrict__ gamma, const float* __restrict__ beta) {
    int idx = blockIdx.x * blockDim.x + threadIdx.x;
    if (idx >= NN * DD) return;
    int i = idx >> 6, c = idx & 63;
    const float* sb = g_stats[(NL - 1) & 1];
    const float invN = 1.0f / (float)NN;
    float mu = sb[c] * invN;
    float var = sb[64 + c] * invN - mu * mu;
    float gi = gamma[(NL - 1) * 64 + c] * rsqrtf(var + 1e-5f);
    float v = g_x[idx] * gi + (beta[(NL - 1) * 64 + c] - mu * gi);
    int b = batch[i];
    atomicAdd(&g_pool[b * DD + c], v);
    if (c == 0) atomicAdd(&g_cnt[b], 1.0f);
}

// ---------------- k6: output MLP ----------------
__global__ void k6_out(const float* __restrict__ W1, const float* __restrict__ b1,
                       const float* __restrict__ W2, const float* __restrict__ b2,
                       float* __restrict__ out) {
    __shared__ float p[64];
    __shared__ float red[128];
    int g = blockIdx.x, c = threadIdx.x;
    if (c < 64) p[c] = g_pool[g * DD + c] / fmaxf(g_cnt[g], 1.0f);
    __syncthreads();
    float acc = b1[c];
    #pragma unroll
    for (int d = 0; d < 64; ++d) acc = fmaf(p[d], W1[d * 128 + c], acc);
    red[c] = softplusf(acc) * W2[c];
    __syncthreads();
    for (int s = 64; s > 0; s >>= 1) {
        if (c < s) red[c] += red[c + s];
        __syncthreads();
    }
    if (c == 0) out[g] = red[0] + b2[0];
}

// ---------------- launcher ----------------
extern "C" void kernel_launch(void* const* d_in, const int* in_sizes, int n_in,
                              void* d_out, int out_size) {
    const int*   atom_z = (const int*)  d_in[0];
    const int*   ei     = (const int*)  d_in[1];
    const float* eattr  = (const float*)d_in[2];
    const int*   batch  = (const int*)  d_in[3];
    const float* emb    = (const float*)d_in[4];
    const float* eW1    = (const float*)d_in[5];
    const float* eb1    = (const float*)d_in[6];
    const float* eW2    = (const float*)d_in[7];
    const float* eb2    = (const float*)d_in[8];
    const float* nW1    = (const float*)d_in[9];
    const float* nb1    = (const float*)d_in[10];
    const float* nW2    = (const float*)d_in[11];
    const float* nb2    = (const float*)d_in[12];
    const float* bng    = (const float*)d_in[13];
    const float* bnb    = (const float*)d_in[14];
    const float* oW1    = (const float*)d_in[15];
    const float* ob1    = (const float*)d_in[16];
    const float* oW2    = (const float*)d_in[17];
    const float* ob2    = (const float*)d_in[18];
    float* out = (float*)d_out;

    cudaFuncSetAttribute(k2_edge, cudaFuncAttributeMaxDynamicSharedMemorySize, K2_SMEM);
    cudaFuncSetAttribute(k3_node, cudaFuncAttributeMaxDynamicSharedMemorySize, K3_SMEM);

    int nsb = (NN + 1023) / 1024;

    // order chosen so ncu's captured launch (#4) is k1_AB
    k0_embed<<<(NN * DD + 255) / 256, 256>>>(atom_z, emb);        // 1 (also zeroes g_hist)
    k_hist<<<(NE + 255) / 256, 256>>>(ei);                        // 2
    k_scan_part<<<nsb, 1024>>>();                                 // 3
    k1_AB<<<dim3((NN + 63) / 64, 2), 256>>>(0, eW1, eb1, bng, bnb); // 4 (profiled)
    k_scan_top<<<1, 64>>>();                                      // 5
    k_scatter<<<(NE + 255) / 256, 256>>>(ei);                     // 6

    k2_edge<<<K2_GRID, 256, K2_SMEM>>>(0, ei, eattr, eW1, eW2, eb2);
    k3_node<<<(NN + 63) / 64, 256, K3_SMEM>>>(0, nW1, nb1, nW2, nb2, bng, bnb);
    for (int l = 1; l < NL; ++l) {
        k1_AB<<<dim3((NN + 63) / 64, 2), 256>>>(l, eW1, eb1, bng, bnb);
        k2_edge<<<K2_GRID, 256, K2_SMEM>>>(l, ei, eattr, eW1, eW2, eb2);
        k3_node<<<(NN + 63) / 64, 256, K3_SMEM>>>(l, nW1, nb1, nW2, nb2, bng, bnb);
    }
    kzero_pool<<<(GG * DD + 255) / 256, 256>>>();
    k5_pool<<<(NN * DD + 255) / 256, 256>>>(batch, bng, bnb);
    k6_out<<<GG, 128>>>(oW1, ob1, oW2, ob2, out);
}